// round 2
// baseline (speedup 1.0000x reference)
#include <cuda_runtime.h>
#include <math.h>
#include <float.h>

// Problem constants
#define PB 2
#define PS 4096
#define PD 2048
#define PH 16
#define PHD 128
#define PW 128
#define PNC 32
#define PT (PB*PS)            // 8192 tokens

// Scratch (allocation-free): Q, K, V, attn-out, each 8192x2048 fp32 = 64 MB
__device__ float g_q [PT * PD];
__device__ float g_k [PT * PD];
__device__ float g_v [PT * PD];
__device__ float g_ao[PT * PD];

// ---------------------------------------------------------------------------
// GEMM: C[m,n] = sum_k A[m,k] * W[n,k]   (A row-major MxK, W row-major NxK)
// 128x128 block tile, BK=16, 256 threads, 8x8 per-thread micro-tile.
// M,N multiples of 128; K multiple of 16. Fully in-bounds by construction.
// ---------------------------------------------------------------------------
__global__ __launch_bounds__(256)
void gemm_tn(const float* __restrict__ A, const float* __restrict__ W,
             float* __restrict__ C, int M, int N, int K)
{
    __shared__ float As[16][128];
    __shared__ float Ws[16][128];

    const int tid = threadIdx.x;
    const int bm  = blockIdx.y * 128;
    const int bn  = blockIdx.x * 128;
    const int tx  = tid & 15;
    const int ty  = tid >> 4;

    float acc[8][8];
#pragma unroll
    for (int i = 0; i < 8; i++)
#pragma unroll
        for (int j = 0; j < 8; j++) acc[i][j] = 0.0f;

    for (int k0 = 0; k0 < K; k0 += 16) {
        // Load A tile (128 rows x 16 k) and W tile, transposed into smem.
#pragma unroll
        for (int l = 0; l < 2; l++) {
            int f  = tid + l * 256;          // 0..511 float4 slots
            int m  = f >> 2;                 // 0..127
            int kq = (f & 3) << 2;           // 0,4,8,12
            float4 va = *(const float4*)&A[(size_t)(bm + m) * K + k0 + kq];
            As[kq + 0][m] = va.x; As[kq + 1][m] = va.y;
            As[kq + 2][m] = va.z; As[kq + 3][m] = va.w;
            float4 vb = *(const float4*)&W[(size_t)(bn + m) * K + k0 + kq];
            Ws[kq + 0][m] = vb.x; Ws[kq + 1][m] = vb.y;
            Ws[kq + 2][m] = vb.z; Ws[kq + 3][m] = vb.w;
        }
        __syncthreads();

#pragma unroll
        for (int kk = 0; kk < 16; kk++) {
            float a[8], b[8];
            *(float4*)&a[0] = *(float4*)&As[kk][ty * 8];
            *(float4*)&a[4] = *(float4*)&As[kk][ty * 8 + 4];
            *(float4*)&b[0] = *(float4*)&Ws[kk][tx * 8];
            *(float4*)&b[4] = *(float4*)&Ws[kk][tx * 8 + 4];
#pragma unroll
            for (int i = 0; i < 8; i++)
#pragma unroll
                for (int j = 0; j < 8; j++)
                    acc[i][j] = fmaf(a[i], b[j], acc[i][j]);
        }
        __syncthreads();
    }

#pragma unroll
    for (int i = 0; i < 8; i++) {
        int r = bm + ty * 8 + i;
        float4* cp = (float4*)&C[(size_t)r * N + bn + tx * 8];
        cp[0] = make_float4(acc[i][0], acc[i][1], acc[i][2], acc[i][3]);
        cp[1] = make_float4(acc[i][4], acc[i][5], acc[i][6], acc[i][7]);
    }
}

// ---------------------------------------------------------------------------
// RoPE on Q and K in place. One thread per (token, head, j<64) pair.
// pos = token % 128 (window-local), inv_freq = 10000^(-2j/128)
// ---------------------------------------------------------------------------
__global__ void rope_kernel(float* __restrict__ q, float* __restrict__ k)
{
    int idx = blockIdx.x * blockDim.x + threadIdx.x;
    const int total = PT * PH * 64;        // 8,388,608
    if (idx >= total) return;
    int j    = idx & 63;
    int rest = idx >> 6;
    int h    = rest & (PH - 1);
    int s    = rest >> 4;
    int w    = s & (PW - 1);

    // freq = w * 10000^(-j/64) = w * exp(-j * ln(10000)/64)
    const float c_ln = 9.210340371976184f / 64.0f;
    float freq = (float)w * expf(-(float)j * c_ln);
    float cv = cosf(freq);
    float sv = sinf(freq);

    int base = s * PD + h * PHD + j;
    float q0 = q[base], q1 = q[base + 64];
    q[base]      = q0 * cv - q1 * sv;
    q[base + 64] = q1 * cv + q0 * sv;
    float k0 = k[base], k1 = k[base + 64];
    k[base]      = k0 * cv - k1 * sv;
    k[base + 64] = k1 * cv + k0 * sv;
}

// ---------------------------------------------------------------------------
// Block-local attention: one CTA per (chunk c, head h, batch b).
// 128 queries x 128 keys x 128 dims, scores+softmax in smem.
// smem: sQ[128][129], sK/V[128][129], sS[128][129] = 198,144 B dynamic.
// ---------------------------------------------------------------------------
__global__ __launch_bounds__(256)
void attn_kernel(const float* __restrict__ Q, const float* __restrict__ K,
                 const float* __restrict__ V, const float* __restrict__ mask,
                 float* __restrict__ O)
{
    extern __shared__ float sm[];
    float* sQ = sm;                 // 128*129
    float* sK = sm + 128 * 129;     // K, later reused for V
    float* sS = sm + 2 * 128 * 129; // scores / probs

    const int c = blockIdx.x;
    const int h = blockIdx.y;
    const int b = blockIdx.z;
    const int tid  = threadIdx.x;
    const int row  = tid & 127;
    const int half = tid >> 7;      // 0 or 1

    const int tb   = b * PS + c * PW;       // first token of this chunk
    const int cbase = h * PHD;              // column base within D

    // Load Q and K tiles (each thread: 16 float4)
#pragma unroll
    for (int l = 0; l < 16; l++) {
        int f  = tid + l * 256;             // 0..4095
        int r  = f >> 5;                    // 0..127
        int d4 = (f & 31) << 2;             // 0..124
        float4 vq = *(const float4*)&Q[(size_t)(tb + r) * PD + cbase + d4];
        sQ[r * 129 + d4 + 0] = vq.x; sQ[r * 129 + d4 + 1] = vq.y;
        sQ[r * 129 + d4 + 2] = vq.z; sQ[r * 129 + d4 + 3] = vq.w;
        float4 vk = *(const float4*)&K[(size_t)(tb + r) * PD + cbase + d4];
        sK[r * 129 + d4 + 0] = vk.x; sK[r * 129 + d4 + 1] = vk.y;
        sK[r * 129 + d4 + 2] = vk.z; sK[r * 129 + d4 + 3] = vk.w;
    }
    __syncthreads();

    // Phase 1: scores[row][k] for k in [half*64, half*64+64)
    const float scale = 0.08838834764831845f;   // 1/sqrt(128)
    const size_t mbase = (size_t)b * PS * PS + (size_t)(c * PW + row) * PS + c * PW;
    const float* qrow = &sQ[row * 129];
    for (int kb = half * 64; kb < half * 64 + 64; kb += 4) {
        float a0 = 0.f, a1 = 0.f, a2 = 0.f, a3 = 0.f;
        const float* k0p = &sK[(kb + 0) * 129];
        const float* k1p = &sK[(kb + 1) * 129];
        const float* k2p = &sK[(kb + 2) * 129];
        const float* k3p = &sK[(kb + 3) * 129];
#pragma unroll 8
        for (int d = 0; d < 128; d++) {
            float qv = qrow[d];
            a0 = fmaf(qv, k0p[d], a0);
            a1 = fmaf(qv, k1p[d], a1);
            a2 = fmaf(qv, k2p[d], a2);
            a3 = fmaf(qv, k3p[d], a3);
        }
        float s0 = fmaxf(a0 * scale + mask[mbase + kb + 0], -3.402823466e38f);
        float s1 = fmaxf(a1 * scale + mask[mbase + kb + 1], -3.402823466e38f);
        float s2 = fmaxf(a2 * scale + mask[mbase + kb + 2], -3.402823466e38f);
        float s3 = fmaxf(a3 * scale + mask[mbase + kb + 3], -3.402823466e38f);
        sS[row * 129 + kb + 0] = s0;
        sS[row * 129 + kb + 1] = s1;
        sS[row * 129 + kb + 2] = s2;
        sS[row * 129 + kb + 3] = s3;
    }
    __syncthreads();

    // Phase 2a: all threads load V over the K buffer.
#pragma unroll
    for (int l = 0; l < 16; l++) {
        int f  = tid + l * 256;
        int r  = f >> 5;
        int d4 = (f & 31) << 2;
        float4 vv = *(const float4*)&V[(size_t)(tb + r) * PD + cbase + d4];
        sK[r * 129 + d4 + 0] = vv.x; sK[r * 129 + d4 + 1] = vv.y;
        sK[r * 129 + d4 + 2] = vv.z; sK[r * 129 + d4 + 3] = vv.w;
    }
    // Phase 2b: softmax per row (threads with half==0 own full rows).
    if (half == 0) {
        float* srow = &sS[row * 129];
        float mx = -FLT_MAX;
#pragma unroll 4
        for (int i = 0; i < 128; i++) mx = fmaxf(mx, srow[i]);
        float sum = 0.f;
#pragma unroll 4
        for (int i = 0; i < 128; i++) {
            float e = __expf(srow[i] - mx);
            srow[i] = e;
            sum += e;
        }
        float inv = 1.0f / sum;
#pragma unroll 4
        for (int i = 0; i < 128; i++) srow[i] *= inv;
    }
    __syncthreads();

    // Phase 3: out[row][d] = sum_k probs[row][k] * V[k][d], d in half's 64-range
    const float* prow = &sS[row * 129];
    for (int d0 = half * 64; d0 < half * 64 + 64; d0 += 4) {
        float a0 = 0.f, a1 = 0.f, a2 = 0.f, a3 = 0.f;
#pragma unroll 4
        for (int kk = 0; kk < 128; kk++) {
            float p = prow[kk];
            const float* vr = &sK[kk * 129 + d0];
            a0 = fmaf(p, vr[0], a0);
            a1 = fmaf(p, vr[1], a1);
            a2 = fmaf(p, vr[2], a2);
            a3 = fmaf(p, vr[3], a3);
        }
        float* op = &O[(size_t)(tb + row) * PD + cbase + d0];
        op[0] = a0; op[1] = a1; op[2] = a2; op[3] = a3;
    }
}

// ---------------------------------------------------------------------------
extern "C" void kernel_launch(void* const* d_in, const int* in_sizes, int n_in,
                              void* d_out, int out_size)
{
    const float* x    = (const float*)d_in[0];
    const float* mask = (const float*)d_in[1];
    const float* wq   = (const float*)d_in[2];
    const float* wk   = (const float*)d_in[3];
    const float* wv   = (const float*)d_in[4];
    const float* wo   = (const float*)d_in[5];
    float* out = (float*)d_out;

    void *pq, *pk, *pv, *pa;
    cudaGetSymbolAddress(&pq, g_q);
    cudaGetSymbolAddress(&pk, g_k);
    cudaGetSymbolAddress(&pv, g_v);
    cudaGetSymbolAddress(&pa, g_ao);
    float* q  = (float*)pq;
    float* k  = (float*)pk;
    float* v  = (float*)pv;
    float* ao = (float*)pa;

    dim3 gblk(PD / 128, PT / 128);   // 16 x 64 = 1024 blocks

    gemm_tn<<<gblk, 256>>>(x, wq, q, PT, PD, PD);
    gemm_tn<<<gblk, 256>>>(x, wk, k, PT, PD, PD);
    gemm_tn<<<gblk, 256>>>(x, wv, v, PT, PD, PD);

    int rope_total = PT * PH * 64;
    rope_kernel<<<(rope_total + 255) / 256, 256>>>(q, k);

    size_t smem = 3 * 128 * 129 * sizeof(float);   // 198,144 B
    cudaFuncSetAttribute(attn_kernel, cudaFuncAttributeMaxDynamicSharedMemorySize,
                         (int)smem);
    attn_kernel<<<dim3(PNC, PH, PB), 256, smem>>>(q, k, v, mask, ao);

    gemm_tn<<<gblk, 256>>>(ao, wo, out, PT, PD, PD);
}

// round 3
// speedup vs baseline: 2.5802x; 2.5802x over previous
#include <cuda_runtime.h>
#include <math.h>
#include <float.h>
#include <stdint.h>

// Problem constants
#define PB 2
#define PS 4096
#define PD 2048
#define PH 16
#define PHD 128
#define PW 128
#define PNC 32
#define PT (PB*PS)            // 8192 tokens

// Scratch (allocation-free)
__device__ float g_q [PT * PD];
__device__ float g_k [PT * PD];
__device__ float g_v [PT * PD];
__device__ float g_ao[PT * PD];

// ---------------------------------------------------------------------------
// tf32 tensor-core GEMM: C[m,n] = sum_k A[m,k] * W[n,k]
// A: MxK row-major, W: NxK row-major (so B^T is col-major k-contiguous).
// CTA tile 128x128, BK=32, 256 threads = 8 warps (2 m x 4 n), warp tile 64x32.
// Double-buffered cp.async pipeline. mma.sync.m16n8k8.tf32.
// ---------------------------------------------------------------------------
#define BM 128
#define BN 128
#define BK 32
#define KSTRIDE 36            // BK + 4 pad (144B rows, 16B aligned, conflict-free)

__device__ __forceinline__ uint32_t f2tf32(float x) {
    uint32_t r;
    asm volatile("cvt.rna.tf32.f32 %0, %1;" : "=r"(r) : "f"(x));
    return r;
}

__device__ __forceinline__ void cp_async16(uint32_t saddr, const void* gptr) {
    asm volatile("cp.async.cg.shared.global [%0], [%1], 16;\n" :: "r"(saddr), "l"(gptr));
}

__device__ __forceinline__ void mma_tf32(float* c, const uint32_t* a, const uint32_t* b) {
    asm volatile(
        "mma.sync.aligned.m16n8k8.row.col.f32.tf32.tf32.f32 "
        "{%0,%1,%2,%3}, {%4,%5,%6,%7}, {%8,%9}, {%0,%1,%2,%3};"
        : "+f"(c[0]), "+f"(c[1]), "+f"(c[2]), "+f"(c[3])
        : "r"(a[0]), "r"(a[1]), "r"(a[2]), "r"(a[3]), "r"(b[0]), "r"(b[1]));
}

__global__ __launch_bounds__(256, 1)
void gemm_tf32(const float* __restrict__ A, const float* __restrict__ W,
               float* __restrict__ C, int M, int N, int K)
{
    extern __shared__ float sm[];
    float* sA = sm;                          // [2][128][36]
    float* sB = sm + 2 * BM * KSTRIDE;       // [2][128][36]

    const int tid  = threadIdx.x;
    const int bm   = blockIdx.y * BM;
    const int bn   = blockIdx.x * BN;
    const int warp = tid >> 5;
    const int lane = tid & 31;
    const int wm   = (warp & 1) * 64;        // warp m offset
    const int wn   = (warp >> 1) * 32;       // warp n offset
    const int lr   = lane >> 2;              // 0..7
    const int lc   = lane & 3;               // 0..3

    // copy mapping: 4 float4 per thread per tile per matrix
    const int row0 = tid >> 3;               // 0..31
    const int c4   = (tid & 7) * 4;          // 0,4,..,28

    float acc[4][4][4];
#pragma unroll
    for (int i = 0; i < 4; i++)
#pragma unroll
        for (int j = 0; j < 4; j++)
#pragma unroll
            for (int r = 0; r < 4; r++) acc[i][j][r] = 0.0f;

    const int T = K / BK;                    // 64 tiles

    // --- async tile loader ---
    auto load_tile = [&](int t, int buf) {
        const int k0 = t * BK;
        float* a_dst = sA + buf * BM * KSTRIDE;
        float* b_dst = sB + buf * BM * KSTRIDE;
#pragma unroll
        for (int i = 0; i < 4; i++) {
            int r = row0 + 32 * i;
            uint32_t sa = (uint32_t)__cvta_generic_to_shared(&a_dst[r * KSTRIDE + c4]);
            cp_async16(sa, &A[(size_t)(bm + r) * K + k0 + c4]);
            uint32_t sb = (uint32_t)__cvta_generic_to_shared(&b_dst[r * KSTRIDE + c4]);
            cp_async16(sb, &W[(size_t)(bn + r) * K + k0 + c4]);
        }
        asm volatile("cp.async.commit_group;\n");
    };

    load_tile(0, 0);

    for (int t = 0; t < T; t++) {
        const int buf = t & 1;
        if (t + 1 < T) {
            load_tile(t + 1, (t + 1) & 1);
            asm volatile("cp.async.wait_group 1;\n");
        } else {
            asm volatile("cp.async.wait_group 0;\n");
        }
        __syncthreads();

        const float* a_s = sA + buf * BM * KSTRIDE;
        const float* b_s = sB + buf * BM * KSTRIDE;

#pragma unroll
        for (int kk = 0; kk < 4; kk++) {
            const int kb = kk * 8;
            uint32_t af[4][4];
#pragma unroll
            for (int mt = 0; mt < 4; mt++) {
                int r = wm + mt * 16 + lr;
                af[mt][0] = f2tf32(a_s[(r    ) * KSTRIDE + kb + lc    ]);
                af[mt][1] = f2tf32(a_s[(r + 8) * KSTRIDE + kb + lc    ]);
                af[mt][2] = f2tf32(a_s[(r    ) * KSTRIDE + kb + lc + 4]);
                af[mt][3] = f2tf32(a_s[(r + 8) * KSTRIDE + kb + lc + 4]);
            }
            uint32_t bf[4][2];
#pragma unroll
            for (int nt = 0; nt < 4; nt++) {
                int n = wn + nt * 8 + lr;
                bf[nt][0] = f2tf32(b_s[n * KSTRIDE + kb + lc    ]);
                bf[nt][1] = f2tf32(b_s[n * KSTRIDE + kb + lc + 4]);
            }
#pragma unroll
            for (int mt = 0; mt < 4; mt++)
#pragma unroll
                for (int nt = 0; nt < 4; nt++)
                    mma_tf32(acc[mt][nt], af[mt], bf[nt]);
        }
        __syncthreads();
    }

    // epilogue: c0/c1 pairs contiguous, rows lr and lr+8
#pragma unroll
    for (int mt = 0; mt < 4; mt++) {
#pragma unroll
        for (int nt = 0; nt < 4; nt++) {
            int r0 = bm + wm + mt * 16 + lr;
            int cc = bn + wn + nt * 8 + 2 * lc;
            *(float2*)&C[(size_t)(r0    ) * N + cc] = make_float2(acc[mt][nt][0], acc[mt][nt][1]);
            *(float2*)&C[(size_t)(r0 + 8) * N + cc] = make_float2(acc[mt][nt][2], acc[mt][nt][3]);
        }
    }
}

// ---------------------------------------------------------------------------
// RoPE on Q and K in place.
// ---------------------------------------------------------------------------
__global__ void rope_kernel(float* __restrict__ q, float* __restrict__ k)
{
    int idx = blockIdx.x * blockDim.x + threadIdx.x;
    const int total = PT * PH * 64;
    if (idx >= total) return;
    int j    = idx & 63;
    int rest = idx >> 6;
    int h    = rest & (PH - 1);
    int s    = rest >> 4;
    int w    = s & (PW - 1);

    const float c_ln = 9.210340371976184f / 64.0f;
    float freq = (float)w * expf(-(float)j * c_ln);
    float cv = cosf(freq);
    float sv = sinf(freq);

    int base = s * PD + h * PHD + j;
    float q0 = q[base], q1 = q[base + 64];
    q[base]      = q0 * cv - q1 * sv;
    q[base + 64] = q1 * cv + q0 * sv;
    float k0 = k[base], k1 = k[base + 64];
    k[base]      = k0 * cv - k1 * sv;
    k[base + 64] = k1 * cv + k0 * sv;
}

// ---------------------------------------------------------------------------
// Block-local attention (fp32), one CTA per (chunk, head, batch).
// ---------------------------------------------------------------------------
__global__ __launch_bounds__(256)
void attn_kernel(const float* __restrict__ Q, const float* __restrict__ K,
                 const float* __restrict__ V, const float* __restrict__ mask,
                 float* __restrict__ O)
{
    extern __shared__ float smf[];
    float* sQ = smf;
    float* sK = smf + 128 * 129;
    float* sS = smf + 2 * 128 * 129;

    const int c = blockIdx.x;
    const int h = blockIdx.y;
    const int b = blockIdx.z;
    const int tid  = threadIdx.x;
    const int row  = tid & 127;
    const int half = tid >> 7;

    const int tb    = b * PS + c * PW;
    const int cbase = h * PHD;

#pragma unroll
    for (int l = 0; l < 16; l++) {
        int f  = tid + l * 256;
        int r  = f >> 5;
        int d4 = (f & 31) << 2;
        float4 vq = *(const float4*)&Q[(size_t)(tb + r) * PD + cbase + d4];
        sQ[r * 129 + d4 + 0] = vq.x; sQ[r * 129 + d4 + 1] = vq.y;
        sQ[r * 129 + d4 + 2] = vq.z; sQ[r * 129 + d4 + 3] = vq.w;
        float4 vk = *(const float4*)&K[(size_t)(tb + r) * PD + cbase + d4];
        sK[r * 129 + d4 + 0] = vk.x; sK[r * 129 + d4 + 1] = vk.y;
        sK[r * 129 + d4 + 2] = vk.z; sK[r * 129 + d4 + 3] = vk.w;
    }
    __syncthreads();

    const float scale = 0.08838834764831845f;
    const size_t mbase = (size_t)b * PS * PS + (size_t)(c * PW + row) * PS + c * PW;
    const float* qrow = &sQ[row * 129];
    for (int kb = half * 64; kb < half * 64 + 64; kb += 4) {
        float a0 = 0.f, a1 = 0.f, a2 = 0.f, a3 = 0.f;
        const float* k0p = &sK[(kb + 0) * 129];
        const float* k1p = &sK[(kb + 1) * 129];
        const float* k2p = &sK[(kb + 2) * 129];
        const float* k3p = &sK[(kb + 3) * 129];
#pragma unroll 8
        for (int d = 0; d < 128; d++) {
            float qv = qrow[d];
            a0 = fmaf(qv, k0p[d], a0);
            a1 = fmaf(qv, k1p[d], a1);
            a2 = fmaf(qv, k2p[d], a2);
            a3 = fmaf(qv, k3p[d], a3);
        }
        sS[row * 129 + kb + 0] = fmaxf(a0 * scale + mask[mbase + kb + 0], -3.402823466e38f);
        sS[row * 129 + kb + 1] = fmaxf(a1 * scale + mask[mbase + kb + 1], -3.402823466e38f);
        sS[row * 129 + kb + 2] = fmaxf(a2 * scale + mask[mbase + kb + 2], -3.402823466e38f);
        sS[row * 129 + kb + 3] = fmaxf(a3 * scale + mask[mbase + kb + 3], -3.402823466e38f);
    }
    __syncthreads();

#pragma unroll
    for (int l = 0; l < 16; l++) {
        int f  = tid + l * 256;
        int r  = f >> 5;
        int d4 = (f & 31) << 2;
        float4 vv = *(const float4*)&V[(size_t)(tb + r) * PD + cbase + d4];
        sK[r * 129 + d4 + 0] = vv.x; sK[r * 129 + d4 + 1] = vv.y;
        sK[r * 129 + d4 + 2] = vv.z; sK[r * 129 + d4 + 3] = vv.w;
    }
    if (half == 0) {
        float* srow = &sS[row * 129];
        float mx = -FLT_MAX;
#pragma unroll 4
        for (int i = 0; i < 128; i++) mx = fmaxf(mx, srow[i]);
        float sum = 0.f;
#pragma unroll 4
        for (int i = 0; i < 128; i++) {
            float e = __expf(srow[i] - mx);
            srow[i] = e;
            sum += e;
        }
        float inv = 1.0f / sum;
#pragma unroll 4
        for (int i = 0; i < 128; i++) srow[i] *= inv;
    }
    __syncthreads();

    const float* prow = &sS[row * 129];
    for (int d0 = half * 64; d0 < half * 64 + 64; d0 += 4) {
        float a0 = 0.f, a1 = 0.f, a2 = 0.f, a3 = 0.f;
#pragma unroll 4
        for (int kk = 0; kk < 128; kk++) {
            float p = prow[kk];
            const float* vr = &sK[kk * 129 + d0];
            a0 = fmaf(p, vr[0], a0);
            a1 = fmaf(p, vr[1], a1);
            a2 = fmaf(p, vr[2], a2);
            a3 = fmaf(p, vr[3], a3);
        }
        float* op = &O[(size_t)(tb + row) * PD + cbase + d0];
        op[0] = a0; op[1] = a1; op[2] = a2; op[3] = a3;
    }
}

// ---------------------------------------------------------------------------
extern "C" void kernel_launch(void* const* d_in, const int* in_sizes, int n_in,
                              void* d_out, int out_size)
{
    const float* x    = (const float*)d_in[0];
    const float* mask = (const float*)d_in[1];
    const float* wq   = (const float*)d_in[2];
    const float* wk   = (const float*)d_in[3];
    const float* wv   = (const float*)d_in[4];
    const float* wo   = (const float*)d_in[5];
    float* out = (float*)d_out;

    void *pq, *pk, *pv, *pa;
    cudaGetSymbolAddress(&pq, g_q);
    cudaGetSymbolAddress(&pk, g_k);
    cudaGetSymbolAddress(&pv, g_v);
    cudaGetSymbolAddress(&pa, g_ao);
    float* q  = (float*)pq;
    float* k  = (float*)pk;
    float* v  = (float*)pv;
    float* ao = (float*)pa;

    dim3 gblk(PD / BN, PT / BM);             // 16 x 64

    size_t gsmem = (size_t)4 * BM * KSTRIDE * sizeof(float);   // 73,728 B
    static int configured = -1;
    cudaFuncSetAttribute(gemm_tf32, cudaFuncAttributeMaxDynamicSharedMemorySize,
                         (int)gsmem);
    (void)configured;

    gemm_tf32<<<gblk, 256, gsmem>>>(x, wq, q, PT, PD, PD);
    gemm_tf32<<<gblk, 256, gsmem>>>(x, wk, k, PT, PD, PD);
    gemm_tf32<<<gblk, 256, gsmem>>>(x, wv, v, PT, PD, PD);

    int rope_total = PT * PH * 64;
    rope_kernel<<<(rope_total + 255) / 256, 256>>>(q, k);

    size_t asmem = 3 * 128 * 129 * sizeof(float);
    cudaFuncSetAttribute(attn_kernel, cudaFuncAttributeMaxDynamicSharedMemorySize,
                         (int)asmem);
    attn_kernel<<<dim3(PNC, PH, PB), 256, asmem>>>(q, k, v, mask, ao);

    gemm_tf32<<<gblk, 256, gsmem>>>(ao, wo, out, PT, PD, PD);
}

// round 5
// speedup vs baseline: 2.9547x; 1.1451x over previous
#include <cuda_runtime.h>
#include <math.h>
#include <float.h>
#include <stdint.h>

// Problem constants
#define PB 2
#define PS 4096
#define PD 2048
#define PH 16
#define PHD 128
#define PW 128
#define PNC 32
#define PT (PB*PS)            // 8192 tokens

// Scratch (allocation-free)
__device__ float g_q [PT * PD];
__device__ float g_k [PT * PD];
__device__ float g_v [PT * PD];
__device__ float g_ao[PT * PD];
__device__ float g_xr[PT * PD];        // tf32-rounded x
__device__ float g_wr[4 * PD * PD];    // tf32-rounded wq,wk,wv,wo

__device__ __forceinline__ uint32_t f2tf32(float x) {
    uint32_t r;
    asm("cvt.rna.tf32.f32 %0, %1;" : "=r"(r) : "f"(x));
    return r;
}

// ---------------------------------------------------------------------------
// tf32 tensor-core GEMM: C[m,n] = sum_k A[m,k] * W[n,k]
// Operands are PRE-ROUNDED to tf32 (low mantissa zeroed) so fragments are
// loaded bitwise from smem — no cvt in the inner loop.
// CTA tile 128x128, BK=32, 256 threads = 8 warps (2 m x 4 n), warp tile 64x32.
// Double-buffered cp.async. mma.sync.m16n8k8.tf32. 2 CTAs/SM.
// ---------------------------------------------------------------------------
#define BM 128
#define BN 128
#define BK 32
#define KSTRIDE 36            // BK + 4 pad

__device__ __forceinline__ void cp_async16(uint32_t saddr, const void* gptr) {
    asm volatile("cp.async.cg.shared.global [%0], [%1], 16;\n" :: "r"(saddr), "l"(gptr));
}

__device__ __forceinline__ void mma_tf32(float* c, const uint32_t* a, const uint32_t* b) {
    asm volatile(
        "mma.sync.aligned.m16n8k8.row.col.f32.tf32.tf32.f32 "
        "{%0,%1,%2,%3}, {%4,%5,%6,%7}, {%8,%9}, {%0,%1,%2,%3};"
        : "+f"(c[0]), "+f"(c[1]), "+f"(c[2]), "+f"(c[3])
        : "r"(a[0]), "r"(a[1]), "r"(a[2]), "r"(a[3]), "r"(b[0]), "r"(b[1]));
}

__global__ __launch_bounds__(256, 2)
void gemm_tf32(const float* __restrict__ A, const float* __restrict__ W,
               float* __restrict__ C, int M, int N, int K)
{
    extern __shared__ float sm[];
    float* sA = sm;                          // [2][128][36]
    float* sB = sm + 2 * BM * KSTRIDE;       // [2][128][36]

    const int tid  = threadIdx.x;
    const int bm   = blockIdx.y * BM;
    const int bn   = blockIdx.x * BN;
    const int warp = tid >> 5;
    const int lane = tid & 31;
    const int wm   = (warp & 1) * 64;        // warp m offset
    const int wn   = (warp >> 1) * 32;       // warp n offset
    const int lr   = lane >> 2;              // 0..7
    const int lc   = lane & 3;               // 0..3

    const int row0 = tid >> 3;               // 0..31
    const int c4   = (tid & 7) * 4;          // 0,4,..,28

    float acc[4][4][4];
#pragma unroll
    for (int i = 0; i < 4; i++)
#pragma unroll
        for (int j = 0; j < 4; j++)
#pragma unroll
            for (int r = 0; r < 4; r++) acc[i][j][r] = 0.0f;

    const int T = K / BK;

    auto load_tile = [&](int t, int buf) {
        const int k0 = t * BK;
        float* a_dst = sA + buf * BM * KSTRIDE;
        float* b_dst = sB + buf * BM * KSTRIDE;
#pragma unroll
        for (int i = 0; i < 4; i++) {
            int r = row0 + 32 * i;
            uint32_t sa = (uint32_t)__cvta_generic_to_shared(&a_dst[r * KSTRIDE + c4]);
            cp_async16(sa, &A[(size_t)(bm + r) * K + k0 + c4]);
            uint32_t sb = (uint32_t)__cvta_generic_to_shared(&b_dst[r * KSTRIDE + c4]);
            cp_async16(sb, &W[(size_t)(bn + r) * K + k0 + c4]);
        }
        asm volatile("cp.async.commit_group;\n");
    };

    load_tile(0, 0);

    for (int t = 0; t < T; t++) {
        const int buf = t & 1;
        if (t + 1 < T) {
            load_tile(t + 1, (t + 1) & 1);
            asm volatile("cp.async.wait_group 1;\n");
        } else {
            asm volatile("cp.async.wait_group 0;\n");
        }
        __syncthreads();

        const uint32_t* a_s = (const uint32_t*)(sA + buf * BM * KSTRIDE);
        const uint32_t* b_s = (const uint32_t*)(sB + buf * BM * KSTRIDE);

#pragma unroll
        for (int kk = 0; kk < 4; kk++) {
            const int kb = kk * 8;
            uint32_t af[4][4];
#pragma unroll
            for (int mt = 0; mt < 4; mt++) {
                int r = wm + mt * 16 + lr;
                af[mt][0] = a_s[(r    ) * KSTRIDE + kb + lc    ];
                af[mt][1] = a_s[(r + 8) * KSTRIDE + kb + lc    ];
                af[mt][2] = a_s[(r    ) * KSTRIDE + kb + lc + 4];
                af[mt][3] = a_s[(r + 8) * KSTRIDE + kb + lc + 4];
            }
            uint32_t bf[4][2];
#pragma unroll
            for (int nt = 0; nt < 4; nt++) {
                int n = wn + nt * 8 + lr;
                bf[nt][0] = b_s[n * KSTRIDE + kb + lc    ];
                bf[nt][1] = b_s[n * KSTRIDE + kb + lc + 4];
            }
#pragma unroll
            for (int mt = 0; mt < 4; mt++)
#pragma unroll
                for (int nt = 0; nt < 4; nt++)
                    mma_tf32(acc[mt][nt], af[mt], bf[nt]);
        }
        __syncthreads();
    }

#pragma unroll
    for (int mt = 0; mt < 4; mt++) {
#pragma unroll
        for (int nt = 0; nt < 4; nt++) {
            int r0 = bm + wm + mt * 16 + lr;
            int cc = bn + wn + nt * 8 + 2 * lc;
            *(float2*)&C[(size_t)(r0    ) * N + cc] = make_float2(acc[mt][nt][0], acc[mt][nt][1]);
            *(float2*)&C[(size_t)(r0 + 8) * N + cc] = make_float2(acc[mt][nt][2], acc[mt][nt][3]);
        }
    }
}

// ---------------------------------------------------------------------------
// tf32 rounding prep (rna) — elementwise float4 pass
// ---------------------------------------------------------------------------
__global__ void tf32_round_kernel(const float4* __restrict__ src,
                                  float4* __restrict__ dst, int n4)
{
    int i = blockIdx.x * blockDim.x + threadIdx.x;
    if (i >= n4) return;
    float4 v = src[i];
    v.x = __uint_as_float(f2tf32(v.x));
    v.y = __uint_as_float(f2tf32(v.y));
    v.z = __uint_as_float(f2tf32(v.z));
    v.w = __uint_as_float(f2tf32(v.w));
    dst[i] = v;
}

// ---------------------------------------------------------------------------
// RoPE on Q and K in place.
// ---------------------------------------------------------------------------
__global__ void rope_kernel(float* __restrict__ q, float* __restrict__ k)
{
    int idx = blockIdx.x * blockDim.x + threadIdx.x;
    const int total = PT * PH * 64;
    if (idx >= total) return;
    int j    = idx & 63;
    int rest = idx >> 6;
    int h    = rest & (PH - 1);
    int s    = rest >> 4;
    int w    = s & (PW - 1);

    const float c_ln = 9.210340371976184f / 64.0f;
    float freq = (float)w * expf(-(float)j * c_ln);
    float cv = cosf(freq);
    float sv = sinf(freq);

    int base = s * PD + h * PHD + j;
    float q0 = q[base], q1 = q[base + 64];
    q[base]      = q0 * cv - q1 * sv;
    q[base + 64] = q1 * cv + q0 * sv;
    float k0 = k[base], k1 = k[base + 64];
    k[base]      = k0 * cv - k1 * sv;
    k[base + 64] = k1 * cv + k0 * sv;
}

// ---------------------------------------------------------------------------
// Block-local attention (fp32), one CTA per (chunk, head, batch).
// Output rounded to tf32 (feeds the final GEMM as the A operand).
// ---------------------------------------------------------------------------
__global__ __launch_bounds__(256)
void attn_kernel(const float* __restrict__ Q, const float* __restrict__ K,
                 const float* __restrict__ V, const float* __restrict__ mask,
                 float* __restrict__ O)
{
    extern __shared__ float smf[];
    float* sQ = smf;
    float* sK = smf + 128 * 129;
    float* sS = smf + 2 * 128 * 129;

    const int c = blockIdx.x;
    const int h = blockIdx.y;
    const int b = blockIdx.z;
    const int tid  = threadIdx.x;
    const int row  = tid & 127;
    const int half = tid >> 7;

    const int tb    = b * PS + c * PW;
    const int cbase = h * PHD;

#pragma unroll
    for (int l = 0; l < 16; l++) {
        int f  = tid + l * 256;
        int r  = f >> 5;
        int d4 = (f & 31) << 2;
        float4 vq = *(const float4*)&Q[(size_t)(tb + r) * PD + cbase + d4];
        sQ[r * 129 + d4 + 0] = vq.x; sQ[r * 129 + d4 + 1] = vq.y;
        sQ[r * 129 + d4 + 2] = vq.z; sQ[r * 129 + d4 + 3] = vq.w;
        float4 vk = *(const float4*)&K[(size_t)(tb + r) * PD + cbase + d4];
        sK[r * 129 + d4 + 0] = vk.x; sK[r * 129 + d4 + 1] = vk.y;
        sK[r * 129 + d4 + 2] = vk.z; sK[r * 129 + d4 + 3] = vk.w;
    }
    __syncthreads();

    const float scale = 0.08838834764831845f;
    const size_t mbase = (size_t)b * PS * PS + (size_t)(c * PW + row) * PS + c * PW;
    const float* qrow = &sQ[row * 129];
    for (int kb = half * 64; kb < half * 64 + 64; kb += 4) {
        float a0 = 0.f, a1 = 0.f, a2 = 0.f, a3 = 0.f;
        const float* k0p = &sK[(kb + 0) * 129];
        const float* k1p = &sK[(kb + 1) * 129];
        const float* k2p = &sK[(kb + 2) * 129];
        const float* k3p = &sK[(kb + 3) * 129];
#pragma unroll 8
        for (int d = 0; d < 128; d++) {
            float qv = qrow[d];
            a0 = fmaf(qv, k0p[d], a0);
            a1 = fmaf(qv, k1p[d], a1);
            a2 = fmaf(qv, k2p[d], a2);
            a3 = fmaf(qv, k3p[d], a3);
        }
        sS[row * 129 + kb + 0] = fmaxf(a0 * scale + mask[mbase + kb + 0], -3.402823466e38f);
        sS[row * 129 + kb + 1] = fmaxf(a1 * scale + mask[mbase + kb + 1], -3.402823466e38f);
        sS[row * 129 + kb + 2] = fmaxf(a2 * scale + mask[mbase + kb + 2], -3.402823466e38f);
        sS[row * 129 + kb + 3] = fmaxf(a3 * scale + mask[mbase + kb + 3], -3.402823466e38f);
    }
    __syncthreads();

#pragma unroll
    for (int l = 0; l < 16; l++) {
        int f  = tid + l * 256;
        int r  = f >> 5;
        int d4 = (f & 31) << 2;
        float4 vv = *(const float4*)&V[(size_t)(tb + r) * PD + cbase + d4];
        sK[r * 129 + d4 + 0] = vv.x; sK[r * 129 + d4 + 1] = vv.y;
        sK[r * 129 + d4 + 2] = vv.z; sK[r * 129 + d4 + 3] = vv.w;
    }
    if (half == 0) {
        float* srow = &sS[row * 129];
        float mx = -FLT_MAX;
#pragma unroll 4
        for (int i = 0; i < 128; i++) mx = fmaxf(mx, srow[i]);
        float sum = 0.f;
#pragma unroll 4
        for (int i = 0; i < 128; i++) {
            float e = __expf(srow[i] - mx);
            srow[i] = e;
            sum += e;
        }
        float inv = 1.0f / sum;
#pragma unroll 4
        for (int i = 0; i < 128; i++) srow[i] *= inv;
    }
    __syncthreads();

    const float* prow = &sS[row * 129];
    for (int d0 = half * 64; d0 < half * 64 + 64; d0 += 4) {
        float a0 = 0.f, a1 = 0.f, a2 = 0.f, a3 = 0.f;
#pragma unroll 4
        for (int kk = 0; kk < 128; kk++) {
            float p = prow[kk];
            const float* vr = &sK[kk * 129 + d0];
            a0 = fmaf(p, vr[0], a0);
            a1 = fmaf(p, vr[1], a1);
            a2 = fmaf(p, vr[2], a2);
            a3 = fmaf(p, vr[3], a3);
        }
        float* op = &O[(size_t)(tb + row) * PD + cbase + d0];
        op[0] = __uint_as_float(f2tf32(a0));
        op[1] = __uint_as_float(f2tf32(a1));
        op[2] = __uint_as_float(f2tf32(a2));
        op[3] = __uint_as_float(f2tf32(a3));
    }
}

// ---------------------------------------------------------------------------
extern "C" void kernel_launch(void* const* d_in, const int* in_sizes, int n_in,
                              void* d_out, int out_size)
{
    const float* x    = (const float*)d_in[0];
    const float* mask = (const float*)d_in[1];
    const float* wq   = (const float*)d_in[2];
    const float* wk   = (const float*)d_in[3];
    const float* wv   = (const float*)d_in[4];
    const float* wo   = (const float*)d_in[5];
    float* out = (float*)d_out;

    void *pq, *pk, *pv, *pa, *pxr, *pwr;
    cudaGetSymbolAddress(&pq,  g_q);
    cudaGetSymbolAddress(&pk,  g_k);
    cudaGetSymbolAddress(&pv,  g_v);
    cudaGetSymbolAddress(&pa,  g_ao);
    cudaGetSymbolAddress(&pxr, g_xr);
    cudaGetSymbolAddress(&pwr, g_wr);
    float* q  = (float*)pq;
    float* k  = (float*)pk;
    float* v  = (float*)pv;
    float* ao = (float*)pa;
    float* xr = (float*)pxr;
    float* wr = (float*)pwr;

    // Pre-round GEMM operands to tf32 (rna)
    {
        int n4x = PT * PD / 4;
        tf32_round_kernel<<<n4x / 256, 256>>>((const float4*)x, (float4*)xr, n4x);
        int n4w = PD * PD / 4;
        tf32_round_kernel<<<n4w / 256, 256>>>((const float4*)wq, (float4*)(wr + 0 * (size_t)PD * PD), n4w);
        tf32_round_kernel<<<n4w / 256, 256>>>((const float4*)wk, (float4*)(wr + 1 * (size_t)PD * PD), n4w);
        tf32_round_kernel<<<n4w / 256, 256>>>((const float4*)wv, (float4*)(wr + 2 * (size_t)PD * PD), n4w);
        tf32_round_kernel<<<n4w / 256, 256>>>((const float4*)wo, (float4*)(wr + 3 * (size_t)PD * PD), n4w);
    }

    dim3 gblk(PD / BN, PT / BM);             // 16 x 64

    size_t gsmem = (size_t)4 * BM * KSTRIDE * sizeof(float);   // 73,728 B
    cudaFuncSetAttribute(gemm_tf32, cudaFuncAttributeMaxDynamicSharedMemorySize,
                         (int)gsmem);

    gemm_tf32<<<gblk, 256, gsmem>>>(xr, wr + 0 * (size_t)PD * PD, q, PT, PD, PD);
    gemm_tf32<<<gblk, 256, gsmem>>>(xr, wr + 1 * (size_t)PD * PD, k, PT, PD, PD);
    gemm_tf32<<<gblk, 256, gsmem>>>(xr, wr + 2 * (size_t)PD * PD, v, PT, PD, PD);

    int rope_total = PT * PH * 64;
    rope_kernel<<<(rope_total + 255) / 256, 256>>>(q, k);

    size_t asmem = 3 * 128 * 129 * sizeof(float);
    cudaFuncSetAttribute(attn_kernel, cudaFuncAttributeMaxDynamicSharedMemorySize,
                         (int)asmem);
    attn_kernel<<<dim3(PNC, PH, PB), 256, asmem>>>(q, k, v, mask, ao);

    gemm_tf32<<<gblk, 256, gsmem>>>(ao, wr + 3 * (size_t)PD * PD, out, PT, PD, PD);
}

// round 6
// speedup vs baseline: 4.5526x; 1.5408x over previous
#include <cuda_runtime.h>
#include <cuda_fp16.h>
#include <math.h>
#include <float.h>
#include <stdint.h>

// Problem constants
#define PB 2
#define PS 4096
#define PD 2048
#define PH 16
#define PHD 128
#define PW 128
#define PNC 32
#define PT (PB*PS)            // 8192 tokens

// Scratch (allocation-free)
__device__ float  g_q [PT * PD];
__device__ float  g_k [PT * PD];
__device__ float  g_v [PT * PD];
__device__ __half g_xh[PT * PD];        // fp16 x
__device__ __half g_wh[4 * (size_t)PD * PD];    // fp16 wq,wk,wv,wo
__device__ __half g_aoh[PT * PD];       // fp16 attention output

// ---------------------------------------------------------------------------
// fp16 tensor-core GEMM: C[m,n] = sum_k A[m,k] * W[n,k]   (fp32 accumulate)
// CTA tile 128x128, BK=64 halves (128B/row), 256 threads = 8 warps (2m x 4n),
// warp tile 64x32. Double-buffered cp.async. mma.sync.m16n8k16.f16.f32.
// ---------------------------------------------------------------------------
#define BM 128
#define BN 128
#define BKH 64                 // K per stage, in halves
#define KST 72                 // BKH + 8 pad (144B rows, conflict-free)

__device__ __forceinline__ void cp_async16(uint32_t saddr, const void* gptr) {
    asm volatile("cp.async.cg.shared.global [%0], [%1], 16;\n" :: "r"(saddr), "l"(gptr));
}

__device__ __forceinline__ void mma_f16(float* c, const uint32_t* a, const uint32_t* b) {
    asm volatile(
        "mma.sync.aligned.m16n8k16.row.col.f32.f16.f16.f32 "
        "{%0,%1,%2,%3}, {%4,%5,%6,%7}, {%8,%9}, {%0,%1,%2,%3};"
        : "+f"(c[0]), "+f"(c[1]), "+f"(c[2]), "+f"(c[3])
        : "r"(a[0]), "r"(a[1]), "r"(a[2]), "r"(a[3]), "r"(b[0]), "r"(b[1]));
}

__global__ __launch_bounds__(256, 2)
void gemm_f16(const __half* __restrict__ A, const __half* __restrict__ W,
              float* __restrict__ C, int M, int N, int K)
{
    extern __shared__ __half smh[];
    __half* sA = smh;                        // [2][128][72]
    __half* sB = smh + 2 * BM * KST;         // [2][128][72]

    const int tid  = threadIdx.x;
    const int bm   = blockIdx.y * BM;
    const int bn   = blockIdx.x * BN;
    const int warp = tid >> 5;
    const int lane = tid & 31;
    const int wm   = (warp & 1) * 64;
    const int wn   = (warp >> 1) * 32;
    const int lr   = lane >> 2;              // 0..7
    const int lc   = lane & 3;               // 0..3

    float acc[4][4][4];
#pragma unroll
    for (int i = 0; i < 4; i++)
#pragma unroll
        for (int j = 0; j < 4; j++)
#pragma unroll
            for (int r = 0; r < 4; r++) acc[i][j][r] = 0.0f;

    const int T = K / BKH;                   // 32 stages

    auto load_tile = [&](int t, int buf) {
        const int k0 = t * BKH;
        __half* a_dst = sA + buf * BM * KST;
        __half* b_dst = sB + buf * BM * KST;
#pragma unroll
        for (int i = 0; i < 8; i++) {
            int c   = tid + i * 256;         // 0..2047 16B chunks
            int isB = c >> 10;
            int idx = c & 1023;
            int r   = idx >> 3;              // 0..127
            int c8  = (idx & 7) * 8;         // half offset in row
            const __half* g = isB ? &W[(size_t)(bn + r) * K + k0 + c8]
                                  : &A[(size_t)(bm + r) * K + k0 + c8];
            __half* d = (isB ? b_dst : a_dst) + r * KST + c8;
            cp_async16((uint32_t)__cvta_generic_to_shared(d), g);
        }
        asm volatile("cp.async.commit_group;\n");
    };

    load_tile(0, 0);

    for (int t = 0; t < T; t++) {
        const int buf = t & 1;
        if (t + 1 < T) {
            load_tile(t + 1, (t + 1) & 1);
            asm volatile("cp.async.wait_group 1;\n");
        } else {
            asm volatile("cp.async.wait_group 0;\n");
        }
        __syncthreads();

        const __half* a_s = sA + buf * BM * KST;
        const __half* b_s = sB + buf * BM * KST;

#pragma unroll
        for (int kk = 0; kk < 4; kk++) {
            const int kb = kk * 16;
            uint32_t af[4][4];
#pragma unroll
            for (int mt = 0; mt < 4; mt++) {
                int r = wm + mt * 16 + lr;
                af[mt][0] = *(const uint32_t*)&a_s[(r    ) * KST + kb + 2 * lc    ];
                af[mt][1] = *(const uint32_t*)&a_s[(r + 8) * KST + kb + 2 * lc    ];
                af[mt][2] = *(const uint32_t*)&a_s[(r    ) * KST + kb + 2 * lc + 8];
                af[mt][3] = *(const uint32_t*)&a_s[(r + 8) * KST + kb + 2 * lc + 8];
            }
            uint32_t bf[4][2];
#pragma unroll
            for (int nt = 0; nt < 4; nt++) {
                int n = wn + nt * 8 + lr;
                bf[nt][0] = *(const uint32_t*)&b_s[n * KST + kb + 2 * lc    ];
                bf[nt][1] = *(const uint32_t*)&b_s[n * KST + kb + 2 * lc + 8];
            }
#pragma unroll
            for (int mt = 0; mt < 4; mt++)
#pragma unroll
                for (int nt = 0; nt < 4; nt++)
                    mma_f16(acc[mt][nt], af[mt], bf[nt]);
        }
        __syncthreads();
    }

#pragma unroll
    for (int mt = 0; mt < 4; mt++) {
#pragma unroll
        for (int nt = 0; nt < 4; nt++) {
            int r0 = bm + wm + mt * 16 + lr;
            int cc = bn + wn + nt * 8 + 2 * lc;
            *(float2*)&C[(size_t)(r0    ) * N + cc] = make_float2(acc[mt][nt][0], acc[mt][nt][1]);
            *(float2*)&C[(size_t)(r0 + 8) * N + cc] = make_float2(acc[mt][nt][2], acc[mt][nt][3]);
        }
    }
}

// ---------------------------------------------------------------------------
// fp32 -> fp16 conversion prep
// ---------------------------------------------------------------------------
__global__ void cvt_f16_kernel(const float4* __restrict__ src,
                               __half* __restrict__ dst, int n4)
{
    int i = blockIdx.x * blockDim.x + threadIdx.x;
    if (i >= n4) return;
    float4 v = src[i];
    __half2 h0 = __floats2half2_rn(v.x, v.y);
    __half2 h1 = __floats2half2_rn(v.z, v.w);
    uint2 o;
    o.x = *(uint32_t*)&h0;
    o.y = *(uint32_t*)&h1;
    *(uint2*)&dst[(size_t)i * 4] = o;
}

// ---------------------------------------------------------------------------
// RoPE on Q and K in place (fp32).
// ---------------------------------------------------------------------------
__global__ void rope_kernel(float* __restrict__ q, float* __restrict__ k)
{
    int idx = blockIdx.x * blockDim.x + threadIdx.x;
    const int total = PT * PH * 64;
    if (idx >= total) return;
    int j    = idx & 63;
    int rest = idx >> 6;
    int h    = rest & (PH - 1);
    int s    = rest >> 4;
    int w    = s & (PW - 1);

    const float c_ln = 9.210340371976184f / 64.0f;
    float freq = (float)w * expf(-(float)j * c_ln);
    float cv = cosf(freq);
    float sv = sinf(freq);

    int base = s * PD + h * PHD + j;
    float q0 = q[base], q1 = q[base + 64];
    q[base]      = q0 * cv - q1 * sv;
    q[base + 64] = q1 * cv + q0 * sv;
    float k0 = k[base], k1 = k[base + 64];
    k[base]      = k0 * cv - k1 * sv;
    k[base + 64] = k1 * cv + k0 * sv;
}

// ---------------------------------------------------------------------------
// Block-local attention (fp32 math), one CTA per (chunk, head, batch).
// Output written as fp16 (feeds the final fp16 GEMM).
// ---------------------------------------------------------------------------
__global__ __launch_bounds__(256)
void attn_kernel(const float* __restrict__ Q, const float* __restrict__ K,
                 const float* __restrict__ V, const float* __restrict__ mask,
                 __half* __restrict__ O)
{
    extern __shared__ float smf[];
    float* sQ = smf;
    float* sK = smf + 128 * 129;
    float* sS = smf + 2 * 128 * 129;

    const int c = blockIdx.x;
    const int h = blockIdx.y;
    const int b = blockIdx.z;
    const int tid  = threadIdx.x;
    const int row  = tid & 127;
    const int half_id = tid >> 7;

    const int tb    = b * PS + c * PW;
    const int cbase = h * PHD;

#pragma unroll
    for (int l = 0; l < 16; l++) {
        int f  = tid + l * 256;
        int r  = f >> 5;
        int d4 = (f & 31) << 2;
        float4 vq = *(const float4*)&Q[(size_t)(tb + r) * PD + cbase + d4];
        sQ[r * 129 + d4 + 0] = vq.x; sQ[r * 129 + d4 + 1] = vq.y;
        sQ[r * 129 + d4 + 2] = vq.z; sQ[r * 129 + d4 + 3] = vq.w;
        float4 vk = *(const float4*)&K[(size_t)(tb + r) * PD + cbase + d4];
        sK[r * 129 + d4 + 0] = vk.x; sK[r * 129 + d4 + 1] = vk.y;
        sK[r * 129 + d4 + 2] = vk.z; sK[r * 129 + d4 + 3] = vk.w;
    }
    __syncthreads();

    const float scale = 0.08838834764831845f;
    const size_t mbase = (size_t)b * PS * PS + (size_t)(c * PW + row) * PS + c * PW;
    const float* qrow = &sQ[row * 129];
    for (int kb = half_id * 64; kb < half_id * 64 + 64; kb += 4) {
        float a0 = 0.f, a1 = 0.f, a2 = 0.f, a3 = 0.f;
        const float* k0p = &sK[(kb + 0) * 129];
        const float* k1p = &sK[(kb + 1) * 129];
        const float* k2p = &sK[(kb + 2) * 129];
        const float* k3p = &sK[(kb + 3) * 129];
#pragma unroll 8
        for (int d = 0; d < 128; d++) {
            float qv = qrow[d];
            a0 = fmaf(qv, k0p[d], a0);
            a1 = fmaf(qv, k1p[d], a1);
            a2 = fmaf(qv, k2p[d], a2);
            a3 = fmaf(qv, k3p[d], a3);
        }
        sS[row * 129 + kb + 0] = fmaxf(a0 * scale + mask[mbase + kb + 0], -3.402823466e38f);
        sS[row * 129 + kb + 1] = fmaxf(a1 * scale + mask[mbase + kb + 1], -3.402823466e38f);
        sS[row * 129 + kb + 2] = fmaxf(a2 * scale + mask[mbase + kb + 2], -3.402823466e38f);
        sS[row * 129 + kb + 3] = fmaxf(a3 * scale + mask[mbase + kb + 3], -3.402823466e38f);
    }
    __syncthreads();

#pragma unroll
    for (int l = 0; l < 16; l++) {
        int f  = tid + l * 256;
        int r  = f >> 5;
        int d4 = (f & 31) << 2;
        float4 vv = *(const float4*)&V[(size_t)(tb + r) * PD + cbase + d4];
        sK[r * 129 + d4 + 0] = vv.x; sK[r * 129 + d4 + 1] = vv.y;
        sK[r * 129 + d4 + 2] = vv.z; sK[r * 129 + d4 + 3] = vv.w;
    }
    if (half_id == 0) {
        float* srow = &sS[row * 129];
        float mx = -FLT_MAX;
#pragma unroll 4
        for (int i = 0; i < 128; i++) mx = fmaxf(mx, srow[i]);
        float sum = 0.f;
#pragma unroll 4
        for (int i = 0; i < 128; i++) {
            float e = __expf(srow[i] - mx);
            srow[i] = e;
            sum += e;
        }
        float inv = 1.0f / sum;
#pragma unroll 4
        for (int i = 0; i < 128; i++) srow[i] *= inv;
    }
    __syncthreads();

    const float* prow = &sS[row * 129];
    for (int d0 = half_id * 64; d0 < half_id * 64 + 64; d0 += 4) {
        float a0 = 0.f, a1 = 0.f, a2 = 0.f, a3 = 0.f;
#pragma unroll 4
        for (int kk = 0; kk < 128; kk++) {
            float p = prow[kk];
            const float* vr = &sK[kk * 129 + d0];
            a0 = fmaf(p, vr[0], a0);
            a1 = fmaf(p, vr[1], a1);
            a2 = fmaf(p, vr[2], a2);
            a3 = fmaf(p, vr[3], a3);
        }
        __half2 p0 = __floats2half2_rn(a0, a1);
        __half2 p1 = __floats2half2_rn(a2, a3);
        uint2 o;
        o.x = *(uint32_t*)&p0;
        o.y = *(uint32_t*)&p1;
        *(uint2*)&O[(size_t)(tb + row) * PD + cbase + d0] = o;
    }
}

// ---------------------------------------------------------------------------
extern "C" void kernel_launch(void* const* d_in, const int* in_sizes, int n_in,
                              void* d_out, int out_size)
{
    const float* x    = (const float*)d_in[0];
    const float* mask = (const float*)d_in[1];
    const float* wq   = (const float*)d_in[2];
    const float* wk   = (const float*)d_in[3];
    const float* wv   = (const float*)d_in[4];
    const float* wo   = (const float*)d_in[5];
    float* out = (float*)d_out;

    void *pq, *pk, *pv, *pxh, *pwh, *paoh;
    cudaGetSymbolAddress(&pq,   g_q);
    cudaGetSymbolAddress(&pk,   g_k);
    cudaGetSymbolAddress(&pv,   g_v);
    cudaGetSymbolAddress(&pxh,  g_xh);
    cudaGetSymbolAddress(&pwh,  g_wh);
    cudaGetSymbolAddress(&paoh, g_aoh);
    float*  q   = (float*)pq;
    float*  k   = (float*)pk;
    float*  v   = (float*)pv;
    __half* xh  = (__half*)pxh;
    __half* wh  = (__half*)pwh;
    __half* aoh = (__half*)paoh;

    // fp32 -> fp16 prep
    {
        int n4x = PT * PD / 4;
        cvt_f16_kernel<<<n4x / 256, 256>>>((const float4*)x, xh, n4x);
        int n4w = PD * PD / 4;
        cvt_f16_kernel<<<n4w / 256, 256>>>((const float4*)wq, wh + 0 * (size_t)PD * PD, n4w);
        cvt_f16_kernel<<<n4w / 256, 256>>>((const float4*)wk, wh + 1 * (size_t)PD * PD, n4w);
        cvt_f16_kernel<<<n4w / 256, 256>>>((const float4*)wv, wh + 2 * (size_t)PD * PD, n4w);
        cvt_f16_kernel<<<n4w / 256, 256>>>((const float4*)wo, wh + 3 * (size_t)PD * PD, n4w);
    }

    dim3 gblk(PD / BN, PT / BM);             // 16 x 64

    size_t gsmem = (size_t)4 * BM * KST * sizeof(__half);   // 73,728 B
    cudaFuncSetAttribute(gemm_f16, cudaFuncAttributeMaxDynamicSharedMemorySize,
                         (int)gsmem);

    gemm_f16<<<gblk, 256, gsmem>>>(xh, wh + 0 * (size_t)PD * PD, q, PT, PD, PD);
    gemm_f16<<<gblk, 256, gsmem>>>(xh, wh + 1 * (size_t)PD * PD, k, PT, PD, PD);
    gemm_f16<<<gblk, 256, gsmem>>>(xh, wh + 2 * (size_t)PD * PD, v, PT, PD, PD);

    int rope_total = PT * PH * 64;
    rope_kernel<<<(rope_total + 255) / 256, 256>>>(q, k);

    size_t asmem = 3 * 128 * 129 * sizeof(float);
    cudaFuncSetAttribute(attn_kernel, cudaFuncAttributeMaxDynamicSharedMemorySize,
                         (int)asmem);
    attn_kernel<<<dim3(PNC, PH, PB), 256, asmem>>>(q, k, v, mask, aoh);

    gemm_f16<<<gblk, 256, gsmem>>>(aoh, wh + 3 * (size_t)PD * PD, out, PT, PD, PD);
}

// round 7
// speedup vs baseline: 7.4652x; 1.6398x over previous
#include <cuda_runtime.h>
#include <cuda_fp16.h>
#include <math.h>
#include <float.h>
#include <stdint.h>

// Problem constants
#define PB 2
#define PS 4096
#define PD 2048
#define PH 16
#define PHD 128
#define PW 128
#define PNC 32
#define PT (PB*PS)            // 8192 tokens

// Scratch (allocation-free)
__device__ float  g_q [PT * PD];
__device__ float  g_k [PT * PD];
__device__ float  g_v [PT * PD];
__device__ __half g_xh[PT * PD];                // fp16 x
__device__ __half g_wh[4 * (size_t)PD * PD];    // fp16 wq,wk,wv,wo
__device__ __half g_aoh[PT * PD];               // fp16 attention output

// ---------------------------------------------------------------------------
// PTX helpers
// ---------------------------------------------------------------------------
__device__ __forceinline__ void cp_async16(uint32_t saddr, const void* gptr) {
    asm volatile("cp.async.cg.shared.global [%0], [%1], 16;\n" :: "r"(saddr), "l"(gptr));
}
__device__ __forceinline__ void mma_f16(float* c, const uint32_t* a, const uint32_t* b) {
    asm volatile(
        "mma.sync.aligned.m16n8k16.row.col.f32.f16.f16.f32 "
        "{%0,%1,%2,%3}, {%4,%5,%6,%7}, {%8,%9}, {%0,%1,%2,%3};"
        : "+f"(c[0]), "+f"(c[1]), "+f"(c[2]), "+f"(c[3])
        : "r"(a[0]), "r"(a[1]), "r"(a[2]), "r"(a[3]), "r"(b[0]), "r"(b[1]));
}
__device__ __forceinline__ void ldsm_x4(uint32_t* r, uint32_t addr) {
    asm volatile("ldmatrix.sync.aligned.m8n8.x4.shared.b16 {%0,%1,%2,%3}, [%4];"
        : "=r"(r[0]), "=r"(r[1]), "=r"(r[2]), "=r"(r[3]) : "r"(addr));
}
__device__ __forceinline__ void ldsm_x4_t(uint32_t* r, uint32_t addr) {
    asm volatile("ldmatrix.sync.aligned.m8n8.x4.trans.shared.b16 {%0,%1,%2,%3}, [%4];"
        : "=r"(r[0]), "=r"(r[1]), "=r"(r[2]), "=r"(r[3]) : "r"(addr));
}

// ---------------------------------------------------------------------------
// fp16 tensor-core GEMM: C[m,n] = sum_k A[m,k] * W[n,k]   (fp32 accumulate)
// CTA 128x128, BK=64 halves, 8 warps (2m x 4n), warp tile 64x32.
// Double-buffered cp.async, ldmatrix fragment loads, m16n8k16 HMMA.
// ---------------------------------------------------------------------------
#define BM 128
#define BN 128
#define BKH 64
#define KST 72                 // BKH + 8 pad (144B rows; ldmatrix conflict-free)

__global__ __launch_bounds__(256, 2)
void gemm_f16(const __half* __restrict__ A, const __half* __restrict__ W,
              float* __restrict__ C, int M, int N, int K)
{
    extern __shared__ __half smh[];
    __half* sA = smh;                        // [2][128][72]
    __half* sB = smh + 2 * BM * KST;

    const int tid  = threadIdx.x;
    const int bm   = blockIdx.y * BM;
    const int bn   = blockIdx.x * BN;
    const int warp = tid >> 5;
    const int lane = tid & 31;
    const int wm   = (warp & 1) * 64;
    const int wn   = (warp >> 1) * 32;
    const int lr   = lane >> 2;
    const int lc   = lane & 3;

    float acc[4][4][4];
#pragma unroll
    for (int i = 0; i < 4; i++)
#pragma unroll
        for (int j = 0; j < 4; j++)
#pragma unroll
            for (int r = 0; r < 4; r++) acc[i][j][r] = 0.0f;

    const int T = K / BKH;

    auto load_tile = [&](int t, int buf) {
        const int k0 = t * BKH;
        __half* a_dst = sA + buf * BM * KST;
        __half* b_dst = sB + buf * BM * KST;
#pragma unroll
        for (int i = 0; i < 8; i++) {
            int c   = tid + i * 256;
            int isB = c >> 10;
            int idx = c & 1023;
            int r   = idx >> 3;
            int c8  = (idx & 7) * 8;
            const __half* g = isB ? &W[(size_t)(bn + r) * K + k0 + c8]
                                  : &A[(size_t)(bm + r) * K + k0 + c8];
            __half* d = (isB ? b_dst : a_dst) + r * KST + c8;
            cp_async16((uint32_t)__cvta_generic_to_shared(d), g);
        }
        asm volatile("cp.async.commit_group;\n");
    };

    load_tile(0, 0);

    // ldmatrix lane address components (halves)
    const int a_r = (lane & 15);
    const int a_c = (lane >> 4) * 8;
    const int b_r = (lane & 7) + (lane >> 4) * 8;
    const int b_c = ((lane >> 3) & 1) * 8;

    for (int t = 0; t < T; t++) {
        const int buf = t & 1;
        if (t + 1 < T) {
            load_tile(t + 1, (t + 1) & 1);
            asm volatile("cp.async.wait_group 1;\n");
        } else {
            asm volatile("cp.async.wait_group 0;\n");
        }
        __syncthreads();

        const __half* a_s = sA + buf * BM * KST;
        const __half* b_s = sB + buf * BM * KST;

#pragma unroll
        for (int kk = 0; kk < 4; kk++) {
            const int kb = kk * 16;
            uint32_t af[4][4];
#pragma unroll
            for (int mt = 0; mt < 4; mt++) {
                uint32_t ad = (uint32_t)__cvta_generic_to_shared(
                    a_s + (wm + mt * 16 + a_r) * KST + kb + a_c);
                ldsm_x4(af[mt], ad);
            }
            uint32_t bf[2][4];
#pragma unroll
            for (int p = 0; p < 2; p++) {
                uint32_t bd = (uint32_t)__cvta_generic_to_shared(
                    b_s + (wn + p * 16 + b_r) * KST + kb + b_c);
                ldsm_x4(bf[p], bd);
            }
#pragma unroll
            for (int mt = 0; mt < 4; mt++)
#pragma unroll
                for (int nt = 0; nt < 4; nt++)
                    mma_f16(acc[mt][nt], af[mt], &bf[nt >> 1][(nt & 1) * 2]);
        }
        __syncthreads();
    }

#pragma unroll
    for (int mt = 0; mt < 4; mt++) {
#pragma unroll
        for (int nt = 0; nt < 4; nt++) {
            int r0 = bm + wm + mt * 16 + lr;
            int cc = bn + wn + nt * 8 + 2 * lc;
            *(float2*)&C[(size_t)(r0    ) * N + cc] = make_float2(acc[mt][nt][0], acc[mt][nt][1]);
            *(float2*)&C[(size_t)(r0 + 8) * N + cc] = make_float2(acc[mt][nt][2], acc[mt][nt][3]);
        }
    }
}

// ---------------------------------------------------------------------------
// fp32 -> fp16 conversion prep
// ---------------------------------------------------------------------------
__global__ void cvt_f16_kernel(const float4* __restrict__ src,
                               __half* __restrict__ dst, int n4)
{
    int i = blockIdx.x * blockDim.x + threadIdx.x;
    if (i >= n4) return;
    float4 v = src[i];
    __half2 h0 = __floats2half2_rn(v.x, v.y);
    __half2 h1 = __floats2half2_rn(v.z, v.w);
    uint2 o;
    o.x = *(uint32_t*)&h0;
    o.y = *(uint32_t*)&h1;
    *(uint2*)&dst[(size_t)i * 4] = o;
}

// ---------------------------------------------------------------------------
// RoPE on Q and K in place (fp32).
// ---------------------------------------------------------------------------
__global__ void rope_kernel(float* __restrict__ q, float* __restrict__ k)
{
    int idx = blockIdx.x * blockDim.x + threadIdx.x;
    const int total = PT * PH * 64;
    if (idx >= total) return;
    int j    = idx & 63;
    int rest = idx >> 6;
    int h    = rest & (PH - 1);
    int s    = rest >> 4;
    int w    = s & (PW - 1);

    const float c_ln = 9.210340371976184f / 64.0f;
    float freq = (float)w * expf(-(float)j * c_ln);
    float cv = cosf(freq);
    float sv = sinf(freq);

    int base = s * PD + h * PHD + j;
    float q0 = q[base], q1 = q[base + 64];
    q[base]      = q0 * cv - q1 * sv;
    q[base + 64] = q1 * cv + q0 * sv;
    float k0 = k[base], k1 = k[base + 64];
    k[base]      = k0 * cv - k1 * sv;
    k[base + 64] = k1 * cv + k0 * sv;
}

// ---------------------------------------------------------------------------
// Tensor-core block-local attention. One CTA per (chunk, head, batch).
// 8 warps; warp w owns query rows [16w, 16w+16). Q,K,V as fp16 in smem,
// S=QK^T via HMMA, register softmax, O=P*V via HMMA (V through ldmatrix.trans).
// ---------------------------------------------------------------------------
#define AST 136                 // smem row stride in halves (272B)

__global__ __launch_bounds__(256, 1)
void attn_mma(const float* __restrict__ Q, const float* __restrict__ K,
              const float* __restrict__ V, const float* __restrict__ mask,
              __half* __restrict__ O)
{
    extern __shared__ __half sh[];
    __half* sQ = sh;                   // [128][136]
    __half* sK = sh + 128 * AST;
    __half* sV = sh + 2 * 128 * AST;

    const int c = blockIdx.x;
    const int h = blockIdx.y;
    const int b = blockIdx.z;
    const int tid  = threadIdx.x;
    const int warp = tid >> 5;
    const int lane = tid & 31;
    const int lr   = lane >> 2;
    const int lc   = lane & 3;
    const int m0   = warp * 16;

    const int tb    = b * PS + c * PW;
    const int cbase = h * PHD;

    // Load Q,K,V tiles: fp32 gmem -> fp16 smem
#pragma unroll
    for (int l = 0; l < 16; l++) {
        int f  = tid + l * 256;
        int r  = f >> 5;
        int d4 = (f & 31) << 2;
        size_t g = (size_t)(tb + r) * PD + cbase + d4;
        float4 vq = *(const float4*)&Q[g];
        float4 vk = *(const float4*)&K[g];
        float4 vv = *(const float4*)&V[g];
        __half2 a0 = __floats2half2_rn(vq.x, vq.y), a1 = __floats2half2_rn(vq.z, vq.w);
        __half2 b0 = __floats2half2_rn(vk.x, vk.y), b1 = __floats2half2_rn(vk.z, vk.w);
        __half2 c0 = __floats2half2_rn(vv.x, vv.y), c1 = __floats2half2_rn(vv.z, vv.w);
        uint2 uq; uq.x = *(uint32_t*)&a0; uq.y = *(uint32_t*)&a1;
        uint2 uk; uk.x = *(uint32_t*)&b0; uk.y = *(uint32_t*)&b1;
        uint2 uv; uv.x = *(uint32_t*)&c0; uv.y = *(uint32_t*)&c1;
        *(uint2*)&sQ[r * AST + d4] = uq;
        *(uint2*)&sK[r * AST + d4] = uk;
        *(uint2*)&sV[r * AST + d4] = uv;
    }
    __syncthreads();

    // ---- Phase 1: S = Q K^T  (16 rows x 128 cols per warp) ----
    float sacc[16][4];
#pragma unroll
    for (int i = 0; i < 16; i++)
#pragma unroll
        for (int j = 0; j < 4; j++) sacc[i][j] = 0.0f;

    const int a_r = m0 + (lane & 15);
    const int a_c = (lane >> 4) * 8;
    const int b_r = (lane & 7) + (lane >> 4) * 8;
    const int b_c = ((lane >> 3) & 1) * 8;

#pragma unroll
    for (int ks = 0; ks < 8; ks++) {
        const int kb = ks * 16;
        uint32_t af[4];
        ldsm_x4(af, (uint32_t)__cvta_generic_to_shared(sQ + a_r * AST + kb + a_c));
#pragma unroll
        for (int p = 0; p < 8; p++) {
            uint32_t bf[4];
            ldsm_x4(bf, (uint32_t)__cvta_generic_to_shared(
                        sK + (p * 16 + b_r) * AST + kb + b_c));
            mma_f16(sacc[2 * p    ], af, bf);
            mma_f16(sacc[2 * p + 1], af, bf + 2);
        }
    }

    // scale + mask + clamp
    const float scale = 0.08838834764831845f;   // 1/sqrt(128)
    const float NEG = -3.402823466e38f;
    const float* mrow0 = mask + (size_t)b * PS * PS
                       + (size_t)(c * PW + m0 + lr) * PS + c * PW;
    const float* mrow1 = mrow0 + 8 * PS;
#pragma unroll
    for (int nt = 0; nt < 16; nt++) {
        float2 mv0 = *(const float2*)&mrow0[nt * 8 + 2 * lc];
        float2 mv1 = *(const float2*)&mrow1[nt * 8 + 2 * lc];
        sacc[nt][0] = fmaxf(fmaf(sacc[nt][0], scale, mv0.x), NEG);
        sacc[nt][1] = fmaxf(fmaf(sacc[nt][1], scale, mv0.y), NEG);
        sacc[nt][2] = fmaxf(fmaf(sacc[nt][2], scale, mv1.x), NEG);
        sacc[nt][3] = fmaxf(fmaf(sacc[nt][3], scale, mv1.y), NEG);
    }

    // ---- softmax over 128 cols (rows m0+lr and m0+lr+8) ----
    float mx0 = -FLT_MAX, mx1 = -FLT_MAX;
#pragma unroll
    for (int nt = 0; nt < 16; nt++) {
        mx0 = fmaxf(mx0, fmaxf(sacc[nt][0], sacc[nt][1]));
        mx1 = fmaxf(mx1, fmaxf(sacc[nt][2], sacc[nt][3]));
    }
    mx0 = fmaxf(mx0, __shfl_xor_sync(0xFFFFFFFF, mx0, 1));
    mx0 = fmaxf(mx0, __shfl_xor_sync(0xFFFFFFFF, mx0, 2));
    mx1 = fmaxf(mx1, __shfl_xor_sync(0xFFFFFFFF, mx1, 1));
    mx1 = fmaxf(mx1, __shfl_xor_sync(0xFFFFFFFF, mx1, 2));

    float sum0 = 0.f, sum1 = 0.f;
#pragma unroll
    for (int nt = 0; nt < 16; nt++) {
        sacc[nt][0] = __expf(sacc[nt][0] - mx0);
        sacc[nt][1] = __expf(sacc[nt][1] - mx0);
        sacc[nt][2] = __expf(sacc[nt][2] - mx1);
        sacc[nt][3] = __expf(sacc[nt][3] - mx1);
        sum0 += sacc[nt][0] + sacc[nt][1];
        sum1 += sacc[nt][2] + sacc[nt][3];
    }
    sum0 += __shfl_xor_sync(0xFFFFFFFF, sum0, 1);
    sum0 += __shfl_xor_sync(0xFFFFFFFF, sum0, 2);
    sum1 += __shfl_xor_sync(0xFFFFFFFF, sum1, 1);
    sum1 += __shfl_xor_sync(0xFFFFFFFF, sum1, 2);
    const float inv0 = 1.0f / sum0;
    const float inv1 = 1.0f / sum1;

    // P fragments (fp16): pf[ks][0..3] is the m16k16 A-operand for key-step ks
    uint32_t pf[8][4];
#pragma unroll
    for (int ks = 0; ks < 8; ks++) {
        __half2 p0 = __floats2half2_rn(sacc[2 * ks][0] * inv0, sacc[2 * ks][1] * inv0);
        __half2 p1 = __floats2half2_rn(sacc[2 * ks][2] * inv1, sacc[2 * ks][3] * inv1);
        __half2 p2 = __floats2half2_rn(sacc[2 * ks + 1][0] * inv0, sacc[2 * ks + 1][1] * inv0);
        __half2 p3 = __floats2half2_rn(sacc[2 * ks + 1][2] * inv1, sacc[2 * ks + 1][3] * inv1);
        pf[ks][0] = *(uint32_t*)&p0;
        pf[ks][1] = *(uint32_t*)&p1;
        pf[ks][2] = *(uint32_t*)&p2;
        pf[ks][3] = *(uint32_t*)&p3;
    }

    // ---- Phase 2: O = P V  (V fragments via ldmatrix.trans) ----
    float oacc[16][4];
#pragma unroll
    for (int i = 0; i < 16; i++)
#pragma unroll
        for (int j = 0; j < 4; j++) oacc[i][j] = 0.0f;

    const int v_r = (lane & 15);
    const int v_c = (lane >> 4) * 8;
#pragma unroll
    for (int ks = 0; ks < 8; ks++) {
        const int kb = ks * 16;
#pragma unroll
        for (int p = 0; p < 8; p++) {
            uint32_t bf[4];
            ldsm_x4_t(bf, (uint32_t)__cvta_generic_to_shared(
                          sV + (kb + v_r) * AST + p * 16 + v_c));
            mma_f16(oacc[2 * p    ], pf[ks], bf);
            mma_f16(oacc[2 * p + 1], pf[ks], bf + 2);
        }
    }

    // ---- store O as fp16 ----
#pragma unroll
    for (int nt = 0; nt < 16; nt++) {
        int col = cbase + nt * 8 + 2 * lc;
        size_t g0 = (size_t)(tb + m0 + lr    ) * PD + col;
        size_t g1 = (size_t)(tb + m0 + lr + 8) * PD + col;
        __half2 o0 = __floats2half2_rn(oacc[nt][0], oacc[nt][1]);
        __half2 o1 = __floats2half2_rn(oacc[nt][2], oacc[nt][3]);
        *(uint32_t*)&O[g0] = *(uint32_t*)&o0;
        *(uint32_t*)&O[g1] = *(uint32_t*)&o1;
    }
}

// ---------------------------------------------------------------------------
extern "C" void kernel_launch(void* const* d_in, const int* in_sizes, int n_in,
                              void* d_out, int out_size)
{
    const float* x    = (const float*)d_in[0];
    const float* mask = (const float*)d_in[1];
    const float* wq   = (const float*)d_in[2];
    const float* wk   = (const float*)d_in[3];
    const float* wv   = (const float*)d_in[4];
    const float* wo   = (const float*)d_in[5];
    float* out = (float*)d_out;

    void *pq, *pk, *pv, *pxh, *pwh, *paoh;
    cudaGetSymbolAddress(&pq,   g_q);
    cudaGetSymbolAddress(&pk,   g_k);
    cudaGetSymbolAddress(&pv,   g_v);
    cudaGetSymbolAddress(&pxh,  g_xh);
    cudaGetSymbolAddress(&pwh,  g_wh);
    cudaGetSymbolAddress(&paoh, g_aoh);
    float*  q   = (float*)pq;
    float*  k   = (float*)pk;
    float*  v   = (float*)pv;
    __half* xh  = (__half*)pxh;
    __half* wh  = (__half*)pwh;
    __half* aoh = (__half*)paoh;

    // fp32 -> fp16 prep
    {
        int n4x = PT * PD / 4;
        cvt_f16_kernel<<<n4x / 256, 256>>>((const float4*)x, xh, n4x);
        int n4w = PD * PD / 4;
        cvt_f16_kernel<<<n4w / 256, 256>>>((const float4*)wq, wh + 0 * (size_t)PD * PD, n4w);
        cvt_f16_kernel<<<n4w / 256, 256>>>((const float4*)wk, wh + 1 * (size_t)PD * PD, n4w);
        cvt_f16_kernel<<<n4w / 256, 256>>>((const float4*)wv, wh + 2 * (size_t)PD * PD, n4w);
        cvt_f16_kernel<<<n4w / 256, 256>>>((const float4*)wo, wh + 3 * (size_t)PD * PD, n4w);
    }

    dim3 gblk(PD / BN, PT / BM);             // 16 x 64

    size_t gsmem = (size_t)4 * BM * KST * sizeof(__half);   // 73,728 B
    cudaFuncSetAttribute(gemm_f16, cudaFuncAttributeMaxDynamicSharedMemorySize,
                         (int)gsmem);

    gemm_f16<<<gblk, 256, gsmem>>>(xh, wh + 0 * (size_t)PD * PD, q, PT, PD, PD);
    gemm_f16<<<gblk, 256, gsmem>>>(xh, wh + 1 * (size_t)PD * PD, k, PT, PD, PD);
    gemm_f16<<<gblk, 256, gsmem>>>(xh, wh + 2 * (size_t)PD * PD, v, PT, PD, PD);

    int rope_total = PT * PH * 64;
    rope_kernel<<<(rope_total + 255) / 256, 256>>>(q, k);

    size_t asmem = (size_t)3 * 128 * AST * sizeof(__half);  // 104,448 B
    cudaFuncSetAttribute(attn_mma, cudaFuncAttributeMaxDynamicSharedMemorySize,
                         (int)asmem);
    attn_mma<<<dim3(PNC, PH, PB), 256, asmem>>>(q, k, v, mask, aoh);

    gemm_f16<<<gblk, 256, gsmem>>>(aoh, wh + 3 * (size_t)PD * PD, out, PT, PD, PD);
}

// round 8
// speedup vs baseline: 7.8177x; 1.0472x over previous
#include <cuda_runtime.h>
#include <cuda_fp16.h>
#include <math.h>
#include <float.h>
#include <stdint.h>

// Problem constants
#define PB 2
#define PS 4096
#define PD 2048
#define PH 16
#define PHD 128
#define PW 128
#define PNC 32
#define PT (PB*PS)            // 8192 tokens

// Scratch (allocation-free)
__device__ float  g_q [PT * PD];
__device__ float  g_k [PT * PD];
__device__ float  g_v [PT * PD];
__device__ __half g_xh[PT * PD];                // fp16 x
__device__ __half g_wh[4 * (size_t)PD * PD];    // fp16 wq,wk,wv,wo
__device__ __half g_aoh[PT * PD];               // fp16 attention output
__device__ float  g_cos[PW * 64];               // rope tables
__device__ float  g_sin[PW * 64];

// ---------------------------------------------------------------------------
// PTX helpers
// ---------------------------------------------------------------------------
__device__ __forceinline__ void cp_async16(uint32_t saddr, const void* gptr) {
    asm volatile("cp.async.cg.shared.global [%0], [%1], 16;\n" :: "r"(saddr), "l"(gptr));
}
__device__ __forceinline__ void mma_f16(float* c, const uint32_t* a, const uint32_t* b) {
    asm volatile(
        "mma.sync.aligned.m16n8k16.row.col.f32.f16.f16.f32 "
        "{%0,%1,%2,%3}, {%4,%5,%6,%7}, {%8,%9}, {%0,%1,%2,%3};"
        : "+f"(c[0]), "+f"(c[1]), "+f"(c[2]), "+f"(c[3])
        : "r"(a[0]), "r"(a[1]), "r"(a[2]), "r"(a[3]), "r"(b[0]), "r"(b[1]));
}
__device__ __forceinline__ void ldsm_x4(uint32_t* r, uint32_t addr) {
    asm volatile("ldmatrix.sync.aligned.m8n8.x4.shared.b16 {%0,%1,%2,%3}, [%4];"
        : "=r"(r[0]), "=r"(r[1]), "=r"(r[2]), "=r"(r[3]) : "r"(addr));
}
__device__ __forceinline__ void ldsm_x4_t(uint32_t* r, uint32_t addr) {
    asm volatile("ldmatrix.sync.aligned.m8n8.x4.trans.shared.b16 {%0,%1,%2,%3}, [%4];"
        : "=r"(r[0]), "=r"(r[1]), "=r"(r[2]), "=r"(r[3]) : "r"(addr));
}

// ---------------------------------------------------------------------------
// fp16 tensor-core GEMM: C[m,n] = sum_k A[m,k] * W[n,k]   (fp32 accumulate)
// CTA 128x128, BK=64 halves, 8 warps (2m x 4n), warp tile 64x32.
// 3-stage circular cp.async pipeline, ONE __syncthreads per stage,
// ldmatrix fragment loads, m16n8k16 HMMA. 2 CTAs/SM.
// ---------------------------------------------------------------------------
#define BM 128
#define BN 128
#define BKH 64
#define KST 72                 // BKH + 8 pad (144B rows; ldmatrix conflict-free)
#define NST 3

__global__ __launch_bounds__(256, 2)
void gemm_f16(const __half* __restrict__ A, const __half* __restrict__ W,
              float* __restrict__ C, int M, int N, int K)
{
    extern __shared__ __half smh[];
    __half* sA = smh;                        // [3][128][72]
    __half* sB = smh + NST * BM * KST;       // [3][128][72]

    const int tid  = threadIdx.x;
    const int bm   = blockIdx.y * BM;
    const int bn   = blockIdx.x * BN;
    const int warp = tid >> 5;
    const int lane = tid & 31;
    const int wm   = (warp & 1) * 64;
    const int wn   = (warp >> 1) * 32;
    const int lr   = lane >> 2;
    const int lc   = lane & 3;

    float acc[4][4][4];
#pragma unroll
    for (int i = 0; i < 4; i++)
#pragma unroll
        for (int j = 0; j < 4; j++)
#pragma unroll
            for (int r = 0; r < 4; r++) acc[i][j][r] = 0.0f;

    const int T = K / BKH;                   // 32

    auto load_tile = [&](int t, int buf) {
        const int k0 = t * BKH;
        __half* a_dst = sA + buf * BM * KST;
        __half* b_dst = sB + buf * BM * KST;
#pragma unroll
        for (int i = 0; i < 8; i++) {
            int c   = tid + i * 256;
            int isB = c >> 10;
            int idx = c & 1023;
            int r   = idx >> 3;
            int c8  = (idx & 7) * 8;
            const __half* g = isB ? &W[(size_t)(bn + r) * K + k0 + c8]
                                  : &A[(size_t)(bm + r) * K + k0 + c8];
            __half* d = (isB ? b_dst : a_dst) + r * KST + c8;
            cp_async16((uint32_t)__cvta_generic_to_shared(d), g);
        }
        asm volatile("cp.async.commit_group;\n");
    };

    load_tile(0, 0);
    load_tile(1, 1);

    // ldmatrix lane address components (halves)
    const int a_r = (lane & 15);
    const int a_c = (lane >> 4) * 8;
    const int b_r = (lane & 7) + (lane >> 4) * 8;
    const int b_c = ((lane >> 3) & 1) * 8;

    int buf = 0;
    for (int t = 0; t < T; t++) {
        if (t < T - 1) { asm volatile("cp.async.wait_group 1;\n"); }
        else           { asm volatile("cp.async.wait_group 0;\n"); }
        __syncthreads();

        if (t + 2 < T) {
            int nb = buf + 2; if (nb >= NST) nb -= NST;
            load_tile(t + 2, nb);
        }

        const __half* a_s = sA + buf * BM * KST;
        const __half* b_s = sB + buf * BM * KST;

#pragma unroll
        for (int kk = 0; kk < 4; kk++) {
            const int kb = kk * 16;
            uint32_t af[4][4];
#pragma unroll
            for (int mt = 0; mt < 4; mt++) {
                uint32_t ad = (uint32_t)__cvta_generic_to_shared(
                    a_s + (wm + mt * 16 + a_r) * KST + kb + a_c);
                ldsm_x4(af[mt], ad);
            }
            uint32_t bf[2][4];
#pragma unroll
            for (int p = 0; p < 2; p++) {
                uint32_t bd = (uint32_t)__cvta_generic_to_shared(
                    b_s + (wn + p * 16 + b_r) * KST + kb + b_c);
                ldsm_x4(bf[p], bd);
            }
#pragma unroll
            for (int mt = 0; mt < 4; mt++)
#pragma unroll
                for (int nt = 0; nt < 4; nt++)
                    mma_f16(acc[mt][nt], af[mt], &bf[nt >> 1][(nt & 1) * 2]);
        }
        buf++; if (buf == NST) buf = 0;
    }

#pragma unroll
    for (int mt = 0; mt < 4; mt++) {
#pragma unroll
        for (int nt = 0; nt < 4; nt++) {
            int r0 = bm + wm + mt * 16 + lr;
            int cc = bn + wn + nt * 8 + 2 * lc;
            *(float2*)&C[(size_t)(r0    ) * N + cc] = make_float2(acc[mt][nt][0], acc[mt][nt][1]);
            *(float2*)&C[(size_t)(r0 + 8) * N + cc] = make_float2(acc[mt][nt][2], acc[mt][nt][3]);
        }
    }
}

// ---------------------------------------------------------------------------
// fp32 -> fp16 conversion prep
// ---------------------------------------------------------------------------
__global__ void cvt_f16_kernel(const float4* __restrict__ src,
                               __half* __restrict__ dst, int n4)
{
    int i = blockIdx.x * blockDim.x + threadIdx.x;
    if (i >= n4) return;
    float4 v = src[i];
    __half2 h0 = __floats2half2_rn(v.x, v.y);
    __half2 h1 = __floats2half2_rn(v.z, v.w);
    uint2 o;
    o.x = *(uint32_t*)&h0;
    o.y = *(uint32_t*)&h1;
    *(uint2*)&dst[(size_t)i * 4] = o;
}

// ---------------------------------------------------------------------------
// RoPE cos/sin tables: [w][j], w in [0,128), j in [0,64).
// ---------------------------------------------------------------------------
__global__ void rope_table_kernel(float* __restrict__ ct, float* __restrict__ st)
{
    int t = blockIdx.x * blockDim.x + threadIdx.x;
    if (t >= PW * 64) return;
    int w = t >> 6;
    int j = t & 63;
    const float c_ln = 9.210340371976184f / 64.0f;
    float freq = (float)w * expf(-(float)j * c_ln);
    ct[t] = cosf(freq);
    st[t] = sinf(freq);
}

// ---------------------------------------------------------------------------
// Tensor-core block-local attention with fused RoPE.
// One CTA per (chunk, head, batch); 8 warps, warp w owns 16 query rows.
// ---------------------------------------------------------------------------
#define AST 136                 // smem row stride in halves (272B)

__global__ __launch_bounds__(256, 1)
void attn_mma(const float* __restrict__ Q, const float* __restrict__ K,
              const float* __restrict__ V, const float* __restrict__ mask,
              const float* __restrict__ ctab, const float* __restrict__ stab,
              __half* __restrict__ O)
{
    extern __shared__ __half sh[];
    __half* sQ = sh;                   // [128][136]
    __half* sK = sh + 128 * AST;
    __half* sV = sh + 2 * 128 * AST;

    const int c = blockIdx.x;
    const int h = blockIdx.y;
    const int b = blockIdx.z;
    const int tid  = threadIdx.x;
    const int warp = tid >> 5;
    const int lane = tid & 31;
    const int lr   = lane >> 2;
    const int lc   = lane & 3;
    const int m0   = warp * 16;

    const int tb    = b * PS + c * PW;
    const int cbase = h * PHD;

    // ---- Load Q,K with fused RoPE (pairs d and d+64 share a row) ----
#pragma unroll
    for (int l = 0; l < 8; l++) {
        int f  = tid + l * 256;            // 0..2047 = 128 rows x 16 chunks
        int r  = f >> 4;
        int d4 = (f & 15) << 2;            // 0..60
        size_t g0 = (size_t)(tb + r) * PD + cbase + d4;
        float4 qa = *(const float4*)&Q[g0];
        float4 qb = *(const float4*)&Q[g0 + 64];
        float4 ka = *(const float4*)&K[g0];
        float4 kb = *(const float4*)&K[g0 + 64];
        float4 cv = *(const float4*)&ctab[r * 64 + d4];
        float4 sv = *(const float4*)&stab[r * 64 + d4];

        float4 qo0, qo1, ko0, ko1;
        qo0.x = qa.x * cv.x - qb.x * sv.x;  qo1.x = qb.x * cv.x + qa.x * sv.x;
        qo0.y = qa.y * cv.y - qb.y * sv.y;  qo1.y = qb.y * cv.y + qa.y * sv.y;
        qo0.z = qa.z * cv.z - qb.z * sv.z;  qo1.z = qb.z * cv.z + qa.z * sv.z;
        qo0.w = qa.w * cv.w - qb.w * sv.w;  qo1.w = qb.w * cv.w + qa.w * sv.w;
        ko0.x = ka.x * cv.x - kb.x * sv.x;  ko1.x = kb.x * cv.x + ka.x * sv.x;
        ko0.y = ka.y * cv.y - kb.y * sv.y;  ko1.y = kb.y * cv.y + ka.y * sv.y;
        ko0.z = ka.z * cv.z - kb.z * sv.z;  ko1.z = kb.z * cv.z + ka.z * sv.z;
        ko0.w = ka.w * cv.w - kb.w * sv.w;  ko1.w = kb.w * cv.w + ka.w * sv.w;

        __half2 h0, h1;
        uint2 u;
        h0 = __floats2half2_rn(qo0.x, qo0.y); h1 = __floats2half2_rn(qo0.z, qo0.w);
        u.x = *(uint32_t*)&h0; u.y = *(uint32_t*)&h1;
        *(uint2*)&sQ[r * AST + d4] = u;
        h0 = __floats2half2_rn(qo1.x, qo1.y); h1 = __floats2half2_rn(qo1.z, qo1.w);
        u.x = *(uint32_t*)&h0; u.y = *(uint32_t*)&h1;
        *(uint2*)&sQ[r * AST + d4 + 64] = u;
        h0 = __floats2half2_rn(ko0.x, ko0.y); h1 = __floats2half2_rn(ko0.z, ko0.w);
        u.x = *(uint32_t*)&h0; u.y = *(uint32_t*)&h1;
        *(uint2*)&sK[r * AST + d4] = u;
        h0 = __floats2half2_rn(ko1.x, ko1.y); h1 = __floats2half2_rn(ko1.z, ko1.w);
        u.x = *(uint32_t*)&h0; u.y = *(uint32_t*)&h1;
        *(uint2*)&sK[r * AST + d4 + 64] = u;
    }
    // ---- Load V ----
#pragma unroll
    for (int l = 0; l < 16; l++) {
        int f  = tid + l * 256;
        int r  = f >> 5;
        int d4 = (f & 31) << 2;
        float4 vv = *(const float4*)&V[(size_t)(tb + r) * PD + cbase + d4];
        __half2 c0 = __floats2half2_rn(vv.x, vv.y), c1 = __floats2half2_rn(vv.z, vv.w);
        uint2 uv; uv.x = *(uint32_t*)&c0; uv.y = *(uint32_t*)&c1;
        *(uint2*)&sV[r * AST + d4] = uv;
    }
    __syncthreads();

    // ---- Phase 1: S = Q K^T ----
    float sacc[16][4];
#pragma unroll
    for (int i = 0; i < 16; i++)
#pragma unroll
        for (int j = 0; j < 4; j++) sacc[i][j] = 0.0f;

    const int a_r = m0 + (lane & 15);
    const int a_c = (lane >> 4) * 8;
    const int b_r = (lane & 7) + (lane >> 4) * 8;
    const int b_c = ((lane >> 3) & 1) * 8;

#pragma unroll
    for (int ks = 0; ks < 8; ks++) {
        const int kb = ks * 16;
        uint32_t af[4];
        ldsm_x4(af, (uint32_t)__cvta_generic_to_shared(sQ + a_r * AST + kb + a_c));
#pragma unroll
        for (int p = 0; p < 8; p++) {
            uint32_t bf[4];
            ldsm_x4(bf, (uint32_t)__cvta_generic_to_shared(
                        sK + (p * 16 + b_r) * AST + kb + b_c));
            mma_f16(sacc[2 * p    ], af, bf);
            mma_f16(sacc[2 * p + 1], af, bf + 2);
        }
    }

    const float scale = 0.08838834764831845f;
    const float NEG = -3.402823466e38f;
    const float* mrow0 = mask + (size_t)b * PS * PS
                       + (size_t)(c * PW + m0 + lr) * PS + c * PW;
    const float* mrow1 = mrow0 + 8 * PS;
#pragma unroll
    for (int nt = 0; nt < 16; nt++) {
        float2 mv0 = *(const float2*)&mrow0[nt * 8 + 2 * lc];
        float2 mv1 = *(const float2*)&mrow1[nt * 8 + 2 * lc];
        sacc[nt][0] = fmaxf(fmaf(sacc[nt][0], scale, mv0.x), NEG);
        sacc[nt][1] = fmaxf(fmaf(sacc[nt][1], scale, mv0.y), NEG);
        sacc[nt][2] = fmaxf(fmaf(sacc[nt][2], scale, mv1.x), NEG);
        sacc[nt][3] = fmaxf(fmaf(sacc[nt][3], scale, mv1.y), NEG);
    }

    // ---- softmax ----
    float mx0 = -FLT_MAX, mx1 = -FLT_MAX;
#pragma unroll
    for (int nt = 0; nt < 16; nt++) {
        mx0 = fmaxf(mx0, fmaxf(sacc[nt][0], sacc[nt][1]));
        mx1 = fmaxf(mx1, fmaxf(sacc[nt][2], sacc[nt][3]));
    }
    mx0 = fmaxf(mx0, __shfl_xor_sync(0xFFFFFFFF, mx0, 1));
    mx0 = fmaxf(mx0, __shfl_xor_sync(0xFFFFFFFF, mx0, 2));
    mx1 = fmaxf(mx1, __shfl_xor_sync(0xFFFFFFFF, mx1, 1));
    mx1 = fmaxf(mx1, __shfl_xor_sync(0xFFFFFFFF, mx1, 2));

    float sum0 = 0.f, sum1 = 0.f;
#pragma unroll
    for (int nt = 0; nt < 16; nt++) {
        sacc[nt][0] = __expf(sacc[nt][0] - mx0);
        sacc[nt][1] = __expf(sacc[nt][1] - mx0);
        sacc[nt][2] = __expf(sacc[nt][2] - mx1);
        sacc[nt][3] = __expf(sacc[nt][3] - mx1);
        sum0 += sacc[nt][0] + sacc[nt][1];
        sum1 += sacc[nt][2] + sacc[nt][3];
    }
    sum0 += __shfl_xor_sync(0xFFFFFFFF, sum0, 1);
    sum0 += __shfl_xor_sync(0xFFFFFFFF, sum0, 2);
    sum1 += __shfl_xor_sync(0xFFFFFFFF, sum1, 1);
    sum1 += __shfl_xor_sync(0xFFFFFFFF, sum1, 2);
    const float inv0 = 1.0f / sum0;
    const float inv1 = 1.0f / sum1;

    uint32_t pf[8][4];
#pragma unroll
    for (int ks = 0; ks < 8; ks++) {
        __half2 p0 = __floats2half2_rn(sacc[2 * ks][0] * inv0, sacc[2 * ks][1] * inv0);
        __half2 p1 = __floats2half2_rn(sacc[2 * ks][2] * inv1, sacc[2 * ks][3] * inv1);
        __half2 p2 = __floats2half2_rn(sacc[2 * ks + 1][0] * inv0, sacc[2 * ks + 1][1] * inv0);
        __half2 p3 = __floats2half2_rn(sacc[2 * ks + 1][2] * inv1, sacc[2 * ks + 1][3] * inv1);
        pf[ks][0] = *(uint32_t*)&p0;
        pf[ks][1] = *(uint32_t*)&p1;
        pf[ks][2] = *(uint32_t*)&p2;
        pf[ks][3] = *(uint32_t*)&p3;
    }

    // ---- Phase 2: O = P V ----
    float oacc[16][4];
#pragma unroll
    for (int i = 0; i < 16; i++)
#pragma unroll
        for (int j = 0; j < 4; j++) oacc[i][j] = 0.0f;

    const int v_r = (lane & 15);
    const int v_c = (lane >> 4) * 8;
#pragma unroll
    for (int ks = 0; ks < 8; ks++) {
        const int kb = ks * 16;
#pragma unroll
        for (int p = 0; p < 8; p++) {
            uint32_t bf[4];
            ldsm_x4_t(bf, (uint32_t)__cvta_generic_to_shared(
                          sV + (kb + v_r) * AST + p * 16 + v_c));
            mma_f16(oacc[2 * p    ], pf[ks], bf);
            mma_f16(oacc[2 * p + 1], pf[ks], bf + 2);
        }
    }

#pragma unroll
    for (int nt = 0; nt < 16; nt++) {
        int col = cbase + nt * 8 + 2 * lc;
        size_t g0 = (size_t)(tb + m0 + lr    ) * PD + col;
        size_t g1 = (size_t)(tb + m0 + lr + 8) * PD + col;
        __half2 o0 = __floats2half2_rn(oacc[nt][0], oacc[nt][1]);
        __half2 o1 = __floats2half2_rn(oacc[nt][2], oacc[nt][3]);
        *(uint32_t*)&O[g0] = *(uint32_t*)&o0;
        *(uint32_t*)&O[g1] = *(uint32_t*)&o1;
    }
}

// ---------------------------------------------------------------------------
extern "C" void kernel_launch(void* const* d_in, const int* in_sizes, int n_in,
                              void* d_out, int out_size)
{
    const float* x    = (const float*)d_in[0];
    const float* mask = (const float*)d_in[1];
    const float* wq   = (const float*)d_in[2];
    const float* wk   = (const float*)d_in[3];
    const float* wv   = (const float*)d_in[4];
    const float* wo   = (const float*)d_in[5];
    float* out = (float*)d_out;

    void *pq, *pk, *pv, *pxh, *pwh, *paoh, *pct, *pst;
    cudaGetSymbolAddress(&pq,   g_q);
    cudaGetSymbolAddress(&pk,   g_k);
    cudaGetSymbolAddress(&pv,   g_v);
    cudaGetSymbolAddress(&pxh,  g_xh);
    cudaGetSymbolAddress(&pwh,  g_wh);
    cudaGetSymbolAddress(&paoh, g_aoh);
    cudaGetSymbolAddress(&pct,  g_cos);
    cudaGetSymbolAddress(&pst,  g_sin);
    float*  q    = (float*)pq;
    float*  k    = (float*)pk;
    float*  v    = (float*)pv;
    __half* xh   = (__half*)pxh;
    __half* wh   = (__half*)pwh;
    __half* aoh  = (__half*)paoh;
    float*  ctab = (float*)pct;
    float*  stab = (float*)pst;

    // Prep: fp16 conversions + rope tables
    {
        int n4x = PT * PD / 4;
        cvt_f16_kernel<<<n4x / 256, 256>>>((const float4*)x, xh, n4x);
        int n4w = PD * PD / 4;
        cvt_f16_kernel<<<n4w / 256, 256>>>((const float4*)wq, wh + 0 * (size_t)PD * PD, n4w);
        cvt_f16_kernel<<<n4w / 256, 256>>>((const float4*)wk, wh + 1 * (size_t)PD * PD, n4w);
        cvt_f16_kernel<<<n4w / 256, 256>>>((const float4*)wv, wh + 2 * (size_t)PD * PD, n4w);
        cvt_f16_kernel<<<n4w / 256, 256>>>((const float4*)wo, wh + 3 * (size_t)PD * PD, n4w);
        rope_table_kernel<<<(PW * 64) / 256, 256>>>(ctab, stab);
    }

    dim3 gblk(PD / BN, PT / BM);             // 16 x 64

    size_t gsmem = (size_t)2 * NST * BM * KST * sizeof(__half);   // 110,592 B
    cudaFuncSetAttribute(gemm_f16, cudaFuncAttributeMaxDynamicSharedMemorySize,
                         (int)gsmem);

    gemm_f16<<<gblk, 256, gsmem>>>(xh, wh + 0 * (size_t)PD * PD, q, PT, PD, PD);
    gemm_f16<<<gblk, 256, gsmem>>>(xh, wh + 1 * (size_t)PD * PD, k, PT, PD, PD);
    gemm_f16<<<gblk, 256, gsmem>>>(xh, wh + 2 * (size_t)PD * PD, v, PT, PD, PD);

    size_t asmem = (size_t)3 * 128 * AST * sizeof(__half);  // 104,448 B
    cudaFuncSetAttribute(attn_mma, cudaFuncAttributeMaxDynamicSharedMemorySize,
                         (int)asmem);
    attn_mma<<<dim3(PNC, PH, PB), 256, asmem>>>(q, k, v, mask, ctab, stab, aoh);

    gemm_f16<<<gblk, 256, gsmem>>>(aoh, wh + 3 * (size_t)PD * PD, out, PT, PD, PD);
}

// round 9
// speedup vs baseline: 8.0609x; 1.0311x over previous
#include <cuda_runtime.h>
#include <cuda_fp16.h>
#include <math.h>
#include <float.h>
#include <stdint.h>

// Problem constants
#define PB 2
#define PS 4096
#define PD 2048
#define PD3 6144              // fused QKV output width
#define PH 16
#define PHD 128
#define PW 128
#define PNC 32
#define PT (PB*PS)            // 8192 tokens

// Scratch (allocation-free)
__device__ __half g_qkv[PT * PD3];              // fused fp16 Q|K|V
__device__ __half g_xh [PT * PD];               // fp16 x
__device__ __half g_wh [4 * (size_t)PD * PD];   // fp16 wq,wk,wv,wo (concat)
__device__ __half g_aoh[PT * PD];               // fp16 attention output
__device__ float  g_cos[PW * 64];               // rope tables
__device__ float  g_sin[PW * 64];

// ---------------------------------------------------------------------------
// PTX helpers
// ---------------------------------------------------------------------------
__device__ __forceinline__ void cp_async16(uint32_t saddr, const void* gptr) {
    asm volatile("cp.async.cg.shared.global [%0], [%1], 16;\n" :: "r"(saddr), "l"(gptr));
}
__device__ __forceinline__ void mma_f16(float* c, const uint32_t* a, const uint32_t* b) {
    asm volatile(
        "mma.sync.aligned.m16n8k16.row.col.f32.f16.f16.f32 "
        "{%0,%1,%2,%3}, {%4,%5,%6,%7}, {%8,%9}, {%0,%1,%2,%3};"
        : "+f"(c[0]), "+f"(c[1]), "+f"(c[2]), "+f"(c[3])
        : "r"(a[0]), "r"(a[1]), "r"(a[2]), "r"(a[3]), "r"(b[0]), "r"(b[1]));
}
__device__ __forceinline__ void ldsm_x4(uint32_t* r, uint32_t addr) {
    asm volatile("ldmatrix.sync.aligned.m8n8.x4.shared.b16 {%0,%1,%2,%3}, [%4];"
        : "=r"(r[0]), "=r"(r[1]), "=r"(r[2]), "=r"(r[3]) : "r"(addr));
}
__device__ __forceinline__ void ldsm_x4_t(uint32_t* r, uint32_t addr) {
    asm volatile("ldmatrix.sync.aligned.m8n8.x4.trans.shared.b16 {%0,%1,%2,%3}, [%4];"
        : "=r"(r[0]), "=r"(r[1]), "=r"(r[2]), "=r"(r[3]) : "r"(addr));
}

// ---------------------------------------------------------------------------
// fp16 tensor-core GEMM: C[m,n] = sum_k A[m,k] * W[n,k]   (fp32 accumulate)
// CTA 128x128, BK=64 halves, 8 warps (2m x 4n), warp tile 64x32.
// 3-stage circular cp.async pipeline, ldmatrix fragments, m16n8k16 HMMA.
// Output type templated (fp16 intermediates / fp32 final).
// ---------------------------------------------------------------------------
#define BM 128
#define BN 128
#define BKH 64
#define KST 72                 // BKH + 8 pad (144B rows; ldmatrix conflict-free)
#define NST 3

template <typename OutT>
__global__ __launch_bounds__(256, 2)
void gemm_f16(const __half* __restrict__ A, const __half* __restrict__ W,
              OutT* __restrict__ C, int M, int N, int K)
{
    extern __shared__ __half smh[];
    __half* sA = smh;                        // [3][128][72]
    __half* sB = smh + NST * BM * KST;

    const int tid  = threadIdx.x;
    const int bm   = blockIdx.y * BM;
    const int bn   = blockIdx.x * BN;
    const int warp = tid >> 5;
    const int lane = tid & 31;
    const int wm   = (warp & 1) * 64;
    const int wn   = (warp >> 1) * 32;
    const int lr   = lane >> 2;
    const int lc   = lane & 3;

    float acc[4][4][4];
#pragma unroll
    for (int i = 0; i < 4; i++)
#pragma unroll
        for (int j = 0; j < 4; j++)
#pragma unroll
            for (int r = 0; r < 4; r++) acc[i][j][r] = 0.0f;

    const int T = K / BKH;                   // 32

    auto load_tile = [&](int t, int buf) {
        const int k0 = t * BKH;
        __half* a_dst = sA + buf * BM * KST;
        __half* b_dst = sB + buf * BM * KST;
#pragma unroll
        for (int i = 0; i < 8; i++) {
            int c   = tid + i * 256;
            int isB = c >> 10;
            int idx = c & 1023;
            int r   = idx >> 3;
            int c8  = (idx & 7) * 8;
            const __half* g = isB ? &W[(size_t)(bn + r) * K + k0 + c8]
                                  : &A[(size_t)(bm + r) * K + k0 + c8];
            __half* d = (isB ? b_dst : a_dst) + r * KST + c8;
            cp_async16((uint32_t)__cvta_generic_to_shared(d), g);
        }
        asm volatile("cp.async.commit_group;\n");
    };

    load_tile(0, 0);
    load_tile(1, 1);

    const int a_r = (lane & 15);
    const int a_c = (lane >> 4) * 8;
    const int b_r = (lane & 7) + (lane >> 4) * 8;
    const int b_c = ((lane >> 3) & 1) * 8;

    int buf = 0;
    for (int t = 0; t < T; t++) {
        if (t < T - 1) { asm volatile("cp.async.wait_group 1;\n"); }
        else           { asm volatile("cp.async.wait_group 0;\n"); }
        __syncthreads();

        if (t + 2 < T) {
            int nb = buf + 2; if (nb >= NST) nb -= NST;
            load_tile(t + 2, nb);
        }

        const __half* a_s = sA + buf * BM * KST;
        const __half* b_s = sB + buf * BM * KST;

#pragma unroll
        for (int kk = 0; kk < 4; kk++) {
            const int kb = kk * 16;
            uint32_t af[4][4];
#pragma unroll
            for (int mt = 0; mt < 4; mt++) {
                uint32_t ad = (uint32_t)__cvta_generic_to_shared(
                    a_s + (wm + mt * 16 + a_r) * KST + kb + a_c);
                ldsm_x4(af[mt], ad);
            }
            uint32_t bf[2][4];
#pragma unroll
            for (int p = 0; p < 2; p++) {
                uint32_t bd = (uint32_t)__cvta_generic_to_shared(
                    b_s + (wn + p * 16 + b_r) * KST + kb + b_c);
                ldsm_x4(bf[p], bd);
            }
#pragma unroll
            for (int mt = 0; mt < 4; mt++)
#pragma unroll
                for (int nt = 0; nt < 4; nt++)
                    mma_f16(acc[mt][nt], af[mt], &bf[nt >> 1][(nt & 1) * 2]);
        }
        buf++; if (buf == NST) buf = 0;
    }

#pragma unroll
    for (int mt = 0; mt < 4; mt++) {
#pragma unroll
        for (int nt = 0; nt < 4; nt++) {
            int r0 = bm + wm + mt * 16 + lr;
            int cc = bn + wn + nt * 8 + 2 * lc;
            if (sizeof(OutT) == 4) {
                float* Cf = (float*)C;
                *(float2*)&Cf[(size_t)(r0    ) * N + cc] = make_float2(acc[mt][nt][0], acc[mt][nt][1]);
                *(float2*)&Cf[(size_t)(r0 + 8) * N + cc] = make_float2(acc[mt][nt][2], acc[mt][nt][3]);
            } else {
                __half* Ch = (__half*)C;
                __half2 h0 = __floats2half2_rn(acc[mt][nt][0], acc[mt][nt][1]);
                __half2 h1 = __floats2half2_rn(acc[mt][nt][2], acc[mt][nt][3]);
                *(uint32_t*)&Ch[(size_t)(r0    ) * N + cc] = *(uint32_t*)&h0;
                *(uint32_t*)&Ch[(size_t)(r0 + 8) * N + cc] = *(uint32_t*)&h1;
            }
        }
    }
}

// ---------------------------------------------------------------------------
// fp32 -> fp16 prep: x
// ---------------------------------------------------------------------------
__global__ void cvt_f16_kernel(const float4* __restrict__ src,
                               __half* __restrict__ dst, int n4)
{
    int i = blockIdx.x * blockDim.x + threadIdx.x;
    if (i >= n4) return;
    float4 v = src[i];
    __half2 h0 = __floats2half2_rn(v.x, v.y);
    __half2 h1 = __floats2half2_rn(v.z, v.w);
    uint2 o;
    o.x = *(uint32_t*)&h0;
    o.y = *(uint32_t*)&h1;
    *(uint2*)&dst[(size_t)i * 4] = o;
}

// All 4 weights in one launch; dst is the concatenated fp16 buffer.
__global__ void cvt_w4_kernel(const float4* __restrict__ w0, const float4* __restrict__ w1,
                              const float4* __restrict__ w2, const float4* __restrict__ w3,
                              __half* __restrict__ dst)
{
    const int n4each = PD * PD / 4;          // 1,048,576
    int i = blockIdx.x * blockDim.x + threadIdx.x;
    if (i >= 4 * n4each) return;
    int sel = i >> 20;                        // i / n4each
    int rem = i & (n4each - 1);
    const float4* s = (sel == 0) ? w0 : (sel == 1) ? w1 : (sel == 2) ? w2 : w3;
    float4 v = s[rem];
    __half2 h0 = __floats2half2_rn(v.x, v.y);
    __half2 h1 = __floats2half2_rn(v.z, v.w);
    uint2 o;
    o.x = *(uint32_t*)&h0;
    o.y = *(uint32_t*)&h1;
    *(uint2*)&dst[(size_t)i * 4] = o;
}

// ---------------------------------------------------------------------------
// RoPE cos/sin tables
// ---------------------------------------------------------------------------
__global__ void rope_table_kernel(float* __restrict__ ct, float* __restrict__ st)
{
    int t = blockIdx.x * blockDim.x + threadIdx.x;
    if (t >= PW * 64) return;
    int w = t >> 6;
    int j = t & 63;
    const float c_ln = 9.210340371976184f / 64.0f;
    float freq = (float)w * expf(-(float)j * c_ln);
    ct[t] = cosf(freq);
    st[t] = sinf(freq);
}

// ---------------------------------------------------------------------------
// Tensor-core block-local attention with fused RoPE, fp16 QKV input.
// One CTA per (chunk, head, batch); 8 warps, warp w owns 16 query rows.
// ---------------------------------------------------------------------------
#define AST 136                 // smem row stride in halves (272B)

__global__ __launch_bounds__(256, 1)
void attn_mma(const __half* __restrict__ QKV, const float* __restrict__ mask,
              const float* __restrict__ ctab, const float* __restrict__ stab,
              __half* __restrict__ O)
{
    extern __shared__ __half sh[];
    __half* sQ = sh;                   // [128][136]
    __half* sK = sh + 128 * AST;
    __half* sV = sh + 2 * 128 * AST;

    const int c = blockIdx.x;
    const int h = blockIdx.y;
    const int b = blockIdx.z;
    const int tid  = threadIdx.x;
    const int warp = tid >> 5;
    const int lane = tid & 31;
    const int lr   = lane >> 2;
    const int lc   = lane & 3;
    const int m0   = warp * 16;

    const int tb    = b * PS + c * PW;
    const int cbase = h * PHD;

    // ---- Load Q,K with fused RoPE (fp16 source; pairs d and d+64) ----
#pragma unroll
    for (int l = 0; l < 8; l++) {
        int f  = tid + l * 256;            // 0..2047 = 128 rows x 16 chunks
        int r  = f >> 4;
        int d4 = (f & 15) << 2;            // 0..60
        size_t g0 = (size_t)(tb + r) * PD3 + cbase + d4;
        uint2 uqa = *(const uint2*)&QKV[g0];
        uint2 uqb = *(const uint2*)&QKV[g0 + 64];
        uint2 uka = *(const uint2*)&QKV[g0 + PD];
        uint2 ukb = *(const uint2*)&QKV[g0 + PD + 64];
        float2 qa01 = __half22float2(*(__half2*)&uqa.x);
        float2 qa23 = __half22float2(*(__half2*)&uqa.y);
        float2 qb01 = __half22float2(*(__half2*)&uqb.x);
        float2 qb23 = __half22float2(*(__half2*)&uqb.y);
        float2 ka01 = __half22float2(*(__half2*)&uka.x);
        float2 ka23 = __half22float2(*(__half2*)&uka.y);
        float2 kb01 = __half22float2(*(__half2*)&ukb.x);
        float2 kb23 = __half22float2(*(__half2*)&ukb.y);
        float4 cv = *(const float4*)&ctab[r * 64 + d4];
        float4 sv = *(const float4*)&stab[r * 64 + d4];

        __half2 h0, h1;
        uint2 u;
        h0 = __floats2half2_rn(qa01.x * cv.x - qb01.x * sv.x,
                               qa01.y * cv.y - qb01.y * sv.y);
        h1 = __floats2half2_rn(qa23.x * cv.z - qb23.x * sv.z,
                               qa23.y * cv.w - qb23.y * sv.w);
        u.x = *(uint32_t*)&h0; u.y = *(uint32_t*)&h1;
        *(uint2*)&sQ[r * AST + d4] = u;
        h0 = __floats2half2_rn(qb01.x * cv.x + qa01.x * sv.x,
                               qb01.y * cv.y + qa01.y * sv.y);
        h1 = __floats2half2_rn(qb23.x * cv.z + qa23.x * sv.z,
                               qb23.y * cv.w + qa23.y * sv.w);
        u.x = *(uint32_t*)&h0; u.y = *(uint32_t*)&h1;
        *(uint2*)&sQ[r * AST + d4 + 64] = u;
        h0 = __floats2half2_rn(ka01.x * cv.x - kb01.x * sv.x,
                               ka01.y * cv.y - kb01.y * sv.y);
        h1 = __floats2half2_rn(ka23.x * cv.z - kb23.x * sv.z,
                               ka23.y * cv.w - kb23.y * sv.w);
        u.x = *(uint32_t*)&h0; u.y = *(uint32_t*)&h1;
        *(uint2*)&sK[r * AST + d4] = u;
        h0 = __floats2half2_rn(kb01.x * cv.x + ka01.x * sv.x,
                               kb01.y * cv.y + ka01.y * sv.y);
        h1 = __floats2half2_rn(kb23.x * cv.z + ka23.x * sv.z,
                               kb23.y * cv.w + ka23.y * sv.w);
        u.x = *(uint32_t*)&h0; u.y = *(uint32_t*)&h1;
        *(uint2*)&sK[r * AST + d4 + 64] = u;
    }
    // ---- Load V (fp16, straight copy) ----
#pragma unroll
    for (int l = 0; l < 8; l++) {
        int f  = tid + l * 256;
        int r  = f >> 4;
        int d4 = (f & 15) << 3;            // 8-half chunks
        uint4 uv = *(const uint4*)&QKV[(size_t)(tb + r) * PD3 + cbase + 2 * PD + d4];
        *(uint4*)&sV[r * AST + d4] = uv;
    }
    __syncthreads();

    // ---- Phase 1: S = Q K^T ----
    float sacc[16][4];
#pragma unroll
    for (int i = 0; i < 16; i++)
#pragma unroll
        for (int j = 0; j < 4; j++) sacc[i][j] = 0.0f;

    const int a_r = m0 + (lane & 15);
    const int a_c = (lane >> 4) * 8;
    const int b_r = (lane & 7) + (lane >> 4) * 8;
    const int b_c = ((lane >> 3) & 1) * 8;

#pragma unroll
    for (int ks = 0; ks < 8; ks++) {
        const int kb = ks * 16;
        uint32_t af[4];
        ldsm_x4(af, (uint32_t)__cvta_generic_to_shared(sQ + a_r * AST + kb + a_c));
#pragma unroll
        for (int p = 0; p < 8; p++) {
            uint32_t bf[4];
            ldsm_x4(bf, (uint32_t)__cvta_generic_to_shared(
                        sK + (p * 16 + b_r) * AST + kb + b_c));
            mma_f16(sacc[2 * p    ], af, bf);
            mma_f16(sacc[2 * p + 1], af, bf + 2);
        }
    }

    const float scale = 0.08838834764831845f;
    const float NEG = -3.402823466e38f;
    const float* mrow0 = mask + (size_t)b * PS * PS
                       + (size_t)(c * PW + m0 + lr) * PS + c * PW;
    const float* mrow1 = mrow0 + 8 * PS;
#pragma unroll
    for (int nt = 0; nt < 16; nt++) {
        float2 mv0 = *(const float2*)&mrow0[nt * 8 + 2 * lc];
        float2 mv1 = *(const float2*)&mrow1[nt * 8 + 2 * lc];
        sacc[nt][0] = fmaxf(fmaf(sacc[nt][0], scale, mv0.x), NEG);
        sacc[nt][1] = fmaxf(fmaf(sacc[nt][1], scale, mv0.y), NEG);
        sacc[nt][2] = fmaxf(fmaf(sacc[nt][2], scale, mv1.x), NEG);
        sacc[nt][3] = fmaxf(fmaf(sacc[nt][3], scale, mv1.y), NEG);
    }

    // ---- softmax ----
    float mx0 = -FLT_MAX, mx1 = -FLT_MAX;
#pragma unroll
    for (int nt = 0; nt < 16; nt++) {
        mx0 = fmaxf(mx0, fmaxf(sacc[nt][0], sacc[nt][1]));
        mx1 = fmaxf(mx1, fmaxf(sacc[nt][2], sacc[nt][3]));
    }
    mx0 = fmaxf(mx0, __shfl_xor_sync(0xFFFFFFFF, mx0, 1));
    mx0 = fmaxf(mx0, __shfl_xor_sync(0xFFFFFFFF, mx0, 2));
    mx1 = fmaxf(mx1, __shfl_xor_sync(0xFFFFFFFF, mx1, 1));
    mx1 = fmaxf(mx1, __shfl_xor_sync(0xFFFFFFFF, mx1, 2));

    float sum0 = 0.f, sum1 = 0.f;
#pragma unroll
    for (int nt = 0; nt < 16; nt++) {
        sacc[nt][0] = __expf(sacc[nt][0] - mx0);
        sacc[nt][1] = __expf(sacc[nt][1] - mx0);
        sacc[nt][2] = __expf(sacc[nt][2] - mx1);
        sacc[nt][3] = __expf(sacc[nt][3] - mx1);
        sum0 += sacc[nt][0] + sacc[nt][1];
        sum1 += sacc[nt][2] + sacc[nt][3];
    }
    sum0 += __shfl_xor_sync(0xFFFFFFFF, sum0, 1);
    sum0 += __shfl_xor_sync(0xFFFFFFFF, sum0, 2);
    sum1 += __shfl_xor_sync(0xFFFFFFFF, sum1, 1);
    sum1 += __shfl_xor_sync(0xFFFFFFFF, sum1, 2);
    const float inv0 = 1.0f / sum0;
    const float inv1 = 1.0f / sum1;

    uint32_t pf[8][4];
#pragma unroll
    for (int ks = 0; ks < 8; ks++) {
        __half2 p0 = __floats2half2_rn(sacc[2 * ks][0] * inv0, sacc[2 * ks][1] * inv0);
        __half2 p1 = __floats2half2_rn(sacc[2 * ks][2] * inv1, sacc[2 * ks][3] * inv1);
        __half2 p2 = __floats2half2_rn(sacc[2 * ks + 1][0] * inv0, sacc[2 * ks + 1][1] * inv0);
        __half2 p3 = __floats2half2_rn(sacc[2 * ks + 1][2] * inv1, sacc[2 * ks + 1][3] * inv1);
        pf[ks][0] = *(uint32_t*)&p0;
        pf[ks][1] = *(uint32_t*)&p1;
        pf[ks][2] = *(uint32_t*)&p2;
        pf[ks][3] = *(uint32_t*)&p3;
    }

    // ---- Phase 2: O = P V ----
    float oacc[16][4];
#pragma unroll
    for (int i = 0; i < 16; i++)
#pragma unroll
        for (int j = 0; j < 4; j++) oacc[i][j] = 0.0f;

    const int v_r = (lane & 15);
    const int v_c = (lane >> 4) * 8;
#pragma unroll
    for (int ks = 0; ks < 8; ks++) {
        const int kb = ks * 16;
#pragma unroll
        for (int p = 0; p < 8; p++) {
            uint32_t bf[4];
            ldsm_x4_t(bf, (uint32_t)__cvta_generic_to_shared(
                          sV + (kb + v_r) * AST + p * 16 + v_c));
            mma_f16(oacc[2 * p    ], pf[ks], bf);
            mma_f16(oacc[2 * p + 1], pf[ks], bf + 2);
        }
    }

#pragma unroll
    for (int nt = 0; nt < 16; nt++) {
        int col = cbase + nt * 8 + 2 * lc;
        size_t g0 = (size_t)(tb + m0 + lr    ) * PD + col;
        size_t g1 = (size_t)(tb + m0 + lr + 8) * PD + col;
        __half2 o0 = __floats2half2_rn(oacc[nt][0], oacc[nt][1]);
        __half2 o1 = __floats2half2_rn(oacc[nt][2], oacc[nt][3]);
        *(uint32_t*)&O[g0] = *(uint32_t*)&o0;
        *(uint32_t*)&O[g1] = *(uint32_t*)&o1;
    }
}

// ---------------------------------------------------------------------------
extern "C" void kernel_launch(void* const* d_in, const int* in_sizes, int n_in,
                              void* d_out, int out_size)
{
    const float* x    = (const float*)d_in[0];
    const float* mask = (const float*)d_in[1];
    const float* wq   = (const float*)d_in[2];
    const float* wk   = (const float*)d_in[3];
    const float* wv   = (const float*)d_in[4];
    const float* wo   = (const float*)d_in[5];
    float* out = (float*)d_out;

    void *pqkv, *pxh, *pwh, *paoh, *pct, *pst;
    cudaGetSymbolAddress(&pqkv, g_qkv);
    cudaGetSymbolAddress(&pxh,  g_xh);
    cudaGetSymbolAddress(&pwh,  g_wh);
    cudaGetSymbolAddress(&paoh, g_aoh);
    cudaGetSymbolAddress(&pct,  g_cos);
    cudaGetSymbolAddress(&pst,  g_sin);
    __half* qkv  = (__half*)pqkv;
    __half* xh   = (__half*)pxh;
    __half* wh   = (__half*)pwh;
    __half* aoh  = (__half*)paoh;
    float*  ctab = (float*)pct;
    float*  stab = (float*)pst;

    // Prep: fp16 conversions + rope tables
    {
        int n4x = PT * PD / 4;
        cvt_f16_kernel<<<n4x / 256, 256>>>((const float4*)x, xh, n4x);
        int n4w_all = 4 * PD * PD / 4;
        cvt_w4_kernel<<<n4w_all / 256, 256>>>((const float4*)wq, (const float4*)wk,
                                              (const float4*)wv, (const float4*)wo, wh);
        rope_table_kernel<<<(PW * 64) / 256, 256>>>(ctab, stab);
    }

    size_t gsmem = (size_t)2 * NST * BM * KST * sizeof(__half);   // 110,592 B
    cudaFuncSetAttribute(gemm_f16<__half>, cudaFuncAttributeMaxDynamicSharedMemorySize,
                         (int)gsmem);
    cudaFuncSetAttribute(gemm_f16<float>, cudaFuncAttributeMaxDynamicSharedMemorySize,
                         (int)gsmem);

    // Fused QKV projection: [8192 x 2048] x [6144 x 2048]^T -> fp16 [8192 x 6144]
    dim3 gqkv(PD3 / BN, PT / BM);            // 48 x 64
    gemm_f16<__half><<<gqkv, 256, gsmem>>>(xh, wh, qkv, PT, PD3, PD);

    // Attention (rope fused in loader)
    size_t asmem = (size_t)3 * 128 * AST * sizeof(__half);  // 104,448 B
    cudaFuncSetAttribute(attn_mma, cudaFuncAttributeMaxDynamicSharedMemorySize,
                         (int)asmem);
    attn_mma<<<dim3(PNC, PH, PB), 256, asmem>>>(qkv, mask, ctab, stab, aoh);

    // Output projection (fp32 out)
    dim3 gout(PD / BN, PT / BM);             // 16 x 64
    gemm_f16<float><<<gout, 256, gsmem>>>(aoh, wh + 3 * (size_t)PD * PD, out, PT, PD, PD);
}